// round 2
// baseline (speedup 1.0000x reference)
#include <cuda_runtime.h>
#include <cstdint>

// ---------------------------------------------------------------------------
// CNF Dopri5 fixed-step solver, fully fused per-block persistent kernel.
// B=8192 samples, D=64, H=256, 10 steps x 6 stages.
// Each block owns 64 samples and runs the whole integration locally.
// ---------------------------------------------------------------------------

#define DB 64
#define HB 256
#define BT 8192
#define NSTEPS 10
#define SB 64            // samples per block
#define SP 68            // padded row length in smem (floats)
#define NTHREADS 256
#define NBLOCKS (BT / SB)   // 128

// Global scratch (static __device__ allocation; no cudaMalloc).
__device__ float g_W1t[DB * HB];        // [d][h]  = W1[h][d]
__device__ float g_W2t[HB * HB];        // [i][j]  = W2[j][i]
__device__ float g_Et [HB * HB];        // [i][j]  = W2[j][i] * G[i][j],  G = W1 @ W3
__device__ float g_W3t[HB * DB];        // [j][d]  = W3[d][j]
__device__ float g_k[5][BT * DB];       // k1..k5 per sample, [stage][s][d] (k6 never re-read)

// Dopri5 tableau. Row st = coefficients for combining k_1..k_{st+1} after stage st.
__constant__ float c_A[6][6] = {
    { 0.2f, 0.f, 0.f, 0.f, 0.f, 0.f },
    { 3.f/40.f, 9.f/40.f, 0.f, 0.f, 0.f, 0.f },
    { 44.f/45.f, -56.f/15.f, 32.f/9.f, 0.f, 0.f, 0.f },
    { 19372.f/6561.f, -25360.f/2187.f, 64448.f/6561.f, -212.f/729.f, 0.f, 0.f },
    { 9017.f/3168.f, -355.f/33.f, 46732.f/5247.f, 49.f/176.f, -5103.f/18656.f, 0.f },
    { 35.f/384.f, 0.f, 500.f/1113.f, 125.f/192.f, -2187.f/6784.f, 11.f/84.f }
};
__constant__ float c_CL[6] = {
    35.f/384.f, 0.f, 500.f/1113.f, 125.f/192.f, -2187.f/6784.f, 11.f/84.f
};

__device__ __forceinline__ float softplusf(float z) {
    // stable: max(z,0) + log1p(exp(-|z|))
    return fmaxf(z, 0.f) + log1pf(__expf(-fabsf(z)));
}
__device__ __forceinline__ float sigm(float z) {
    return 1.f / (1.f + __expf(-z));
}

// ---------------------------------------------------------------------------
// Prep: build transposed weights and the trace matrix E.
// grid = (HB), block = (HB). Block i handles row i; thread j column j.
// ---------------------------------------------------------------------------
__global__ void cnf_prep_kernel(const float* __restrict__ W1,
                                const float* __restrict__ W2,
                                const float* __restrict__ W3) {
    int i = blockIdx.x;    // 0..255
    int j = threadIdx.x;   // 0..255
    float g = 0.f;
    #pragma unroll
    for (int d = 0; d < DB; ++d)
        g += W1[i * DB + d] * W3[d * HB + j];   // G[i][j]
    float w2 = W2[j * HB + i];
    g_W2t[i * HB + j] = w2;
    g_Et [i * HB + j] = w2 * g;
    if (i < DB) g_W1t[i * HB + j] = W1[j * DB + i];
    if (j < DB) g_W3t[i * DB + j] = W3[j * HB + i];
}

// NOTE: parameter names chosen so they can never collide with .x/.y/.z/.w
// member-access tokens inside the expansion (the R1 compile failure).
#define FMA4I(Aarr, boff, wscal, vvec) \
    { Aarr[(boff)+0] += (wscal)*(vvec).x; Aarr[(boff)+1] += (wscal)*(vvec).y; \
      Aarr[(boff)+2] += (wscal)*(vvec).z; Aarr[(boff)+3] += (wscal)*(vvec).w; }

// ---------------------------------------------------------------------------
// Main fused solver. grid = 128, block = 256, dynamic smem ~171 KB.
// ---------------------------------------------------------------------------
__global__ void __launch_bounds__(NTHREADS, 1)
cnf_main_kernel(const float* __restrict__ x,
                const float* __restrict__ ld0,
                const float* __restrict__ b1,
                const float* __restrict__ b2,
                const float* __restrict__ b3,
                const float* __restrict__ Tptr,
                float* __restrict__ out) {
    extern __shared__ float sm[];
    float* yt  = sm;                    // [DB][SP]  current y (transposed [d][s])
    float* yst = yt  + DB * SP;         // [DB][SP]  stage argument
    float* h1t = yst + DB * SP;         // [HB][SP]  softplus(z1), transposed [i][s]
    float* s1t = h1t + HB * SP;         // [HB][SP]  sigmoid(z1)
    float* trs = s1t + HB * SP;         // [SB]      per-sample trace accumulator (this stage)
    float* lds = trs + SB;              // [SB]      logdet accumulator
    float* h2t = h1t;                   // alias: h2 overwrites h1 after phase B

    const int tid   = threadIdx.x;
    const int gbase = blockIdx.x * SB;

    // (d, sg) mapping used for loads/stores/phase C: 16 samples per thread
    const int d  = tid & 63;
    const int sg = tid >> 6;
    const int sbase = sg * 16;

    // phase A mapping: 2 h rows x 32 samples per thread
    const int hpair = (tid & 127) * 2;
    const int soff  = (tid >> 7) * 32;

    // phase B mapping: 4 j x 4 s per thread
    const int jj  = (tid >> 4) * 4;
    const int ssb = (tid & 15) * 4;

    const float dt = Tptr[0] * (1.0f / NSTEPS);

    // ---- init: load y0 (coalesced), logdet ----
    #pragma unroll
    for (int c = 0; c < 16; ++c)
        yt[d * SP + sbase + c] = x[(gbase + sbase + c) * DB + d];
    if (tid < SB) lds[tid] = ld0[gbase + tid];

    for (int step = 0; step < NSTEPS; ++step) {
        // stage-0 argument: yst = yt
        #pragma unroll
        for (int c = 0; c < 16; ++c)
            yst[d * SP + sbase + c] = yt[d * SP + sbase + c];

        for (int st = 0; st < 6; ++st) {
            __syncthreads();   // yst ready, previous stage fully done

            // ================= Phase A: z1 = W1 y + b1 -> h1, s1 ============
            float accA[64];
            #pragma unroll
            for (int i = 0; i < 64; ++i) accA[i] = 0.f;
            #pragma unroll 2
            for (int dd = 0; dd < DB; ++dd) {
                float2 wv = *(const float2*)&g_W1t[dd * HB + hpair];
                #pragma unroll
                for (int q = 0; q < 8; ++q) {
                    float4 yv = *(const float4*)&yst[dd * SP + soff + q * 4];
                    FMA4I(accA, q * 4,      wv.x, yv);
                    FMA4I(accA, 32 + q * 4, wv.y, yv);
                }
            }
            {
                float bv0 = b1[hpair], bv1 = b1[hpair + 1];
                #pragma unroll
                for (int q = 0; q < 8; ++q) {
                    float z0 = accA[q*4+0] + bv0, z1 = accA[q*4+1] + bv0;
                    float z2 = accA[q*4+2] + bv0, z3 = accA[q*4+3] + bv0;
                    *(float4*)&h1t[hpair * SP + soff + q*4] =
                        make_float4(softplusf(z0), softplusf(z1), softplusf(z2), softplusf(z3));
                    *(float4*)&s1t[hpair * SP + soff + q*4] =
                        make_float4(sigm(z0), sigm(z1), sigm(z2), sigm(z3));
                    float u0 = accA[32+q*4+0] + bv1, u1 = accA[32+q*4+1] + bv1;
                    float u2 = accA[32+q*4+2] + bv1, u3 = accA[32+q*4+3] + bv1;
                    *(float4*)&h1t[(hpair+1) * SP + soff + q*4] =
                        make_float4(softplusf(u0), softplusf(u1), softplusf(u2), softplusf(u3));
                    *(float4*)&s1t[(hpair+1) * SP + soff + q*4] =
                        make_float4(sigm(u0), sigm(u1), sigm(u2), sigm(u3));
                }
            }
            if (tid < SB) trs[tid] = 0.f;
            __syncthreads();   // h1/s1 + zeroed trs visible

            // ====== Phase B: z2 = W2 h1 + b2, t = E s1, trace, h2 ===========
            float h2keep[64];
            float trp[4] = {0.f, 0.f, 0.f, 0.f};
            #pragma unroll
            for (int jt = 0; jt < 4; ++jt) {
                const int j0 = jt * 64 + jj;
                float az[16], at_[16];
                #pragma unroll
                for (int i = 0; i < 16; ++i) { az[i] = 0.f; at_[i] = 0.f; }
                const float* w2p = &g_W2t[j0];
                const float* etp = &g_Et [j0];
                #pragma unroll 2
                for (int k = 0; k < HB; ++k) {
                    float4 w2 = *(const float4*)(w2p + k * HB);
                    float4 ev = *(const float4*)(etp + k * HB);
                    float4 hv = *(const float4*)&h1t[k * SP + ssb];
                    float4 sv = *(const float4*)&s1t[k * SP + ssb];
                    FMA4I(az,  0,  w2.x, hv); FMA4I(az,  4,  w2.y, hv);
                    FMA4I(az,  8,  w2.z, hv); FMA4I(az, 12,  w2.w, hv);
                    FMA4I(at_, 0,  ev.x, sv); FMA4I(at_, 4,  ev.y, sv);
                    FMA4I(at_, 8,  ev.z, sv); FMA4I(at_, 12, ev.w, sv);
                }
                #pragma unroll
                for (int a = 0; a < 4; ++a) {
                    float bb = b2[j0 + a];
                    #pragma unroll
                    for (int q = 0; q < 4; ++q) {
                        float z = az[a*4+q] + bb;
                        h2keep[jt*16 + a*4 + q] = softplusf(z);
                        trp[q] += sigm(z) * at_[a*4+q];
                    }
                }
            }
            #pragma unroll
            for (int q = 0; q < 4; ++q) atomicAdd(&trs[ssb + q], trp[q]);
            __syncthreads();   // everyone done with h1t/s1t; trs final

            if (tid < SB) lds[tid] += dt * c_CL[st] * trs[tid];

            // write h2 (transposed [j][s]) over h1t region
            #pragma unroll
            for (int jt = 0; jt < 4; ++jt)
                #pragma unroll
                for (int a = 0; a < 4; ++a)
                    *(float4*)&h2t[(jt*64 + jj + a) * SP + ssb] =
                        make_float4(h2keep[jt*16+a*4+0], h2keep[jt*16+a*4+1],
                                    h2keep[jt*16+a*4+2], h2keep[jt*16+a*4+3]);
            __syncthreads();   // h2t ready

            // ========= Phase C: dy = W3 h2 + b3, store k, stage combine ======
            float acc[16];
            #pragma unroll
            for (int c = 0; c < 16; ++c) acc[c] = 0.f;
            #pragma unroll 2
            for (int j = 0; j < HB; ++j) {
                float w3s = g_W3t[j * DB + d];
                #pragma unroll
                for (int q = 0; q < 4; ++q) {
                    float4 hv = *(const float4*)&h2t[j * SP + sbase + q * 4];
                    FMA4I(acc, q * 4, w3s, hv);
                }
            }
            {
                float b3v = b3[d];
                #pragma unroll
                for (int c = 0; c < 16; ++c) acc[c] += b3v;   // acc = k_{st+1} (dy)
            }
            if (st < 5) {
                #pragma unroll
                for (int c = 0; c < 16; ++c)
                    g_k[st][(gbase + sbase + c) * DB + d] = acc[c];
            }
            // stage combine: next argument (st<5) or final y update (st==5)
            {
                float alast = c_A[st][st];
                #pragma unroll
                for (int c = 0; c < 16; ++c) {
                    int s = sbase + c;
                    float v = alast * acc[c];
                    for (int m = 0; m < st; ++m)
                        v += c_A[st][m] * g_k[m][(gbase + s) * DB + d];
                    v = yt[d * SP + s] + dt * v;
                    if (st < 5) yst[d * SP + s] = v;
                    else        yt [d * SP + s] = v;
                }
            }
        } // stages
    } // steps

    __syncthreads();
    // ---- output: y_f then ld_f ----
    #pragma unroll
    for (int c = 0; c < 16; ++c)
        out[(gbase + sbase + c) * DB + d] = yt[d * SP + sbase + c];
    if (tid < SB) out[BT * DB + gbase + tid] = lds[tid];
}

// ---------------------------------------------------------------------------
// Launch
// ---------------------------------------------------------------------------
#define SMEM_BYTES ((2 * DB * SP + 2 * HB * SP + 2 * SB) * 4)

extern "C" void kernel_launch(void* const* d_in, const int* in_sizes, int n_in,
                              void* d_out, int out_size) {
    const float* x   = (const float*)d_in[0];
    const float* ld0 = (const float*)d_in[1];
    const float* W1  = (const float*)d_in[2];
    const float* b1  = (const float*)d_in[3];
    const float* W2  = (const float*)d_in[4];
    const float* b2  = (const float*)d_in[5];
    const float* W3  = (const float*)d_in[6];
    const float* b3  = (const float*)d_in[7];
    const float* T   = (const float*)d_in[8];
    float* out = (float*)d_out;

    cudaFuncSetAttribute(cnf_main_kernel,
                         cudaFuncAttributeMaxDynamicSharedMemorySize, SMEM_BYTES);

    cnf_prep_kernel<<<HB, HB>>>(W1, W2, W3);
    cnf_main_kernel<<<NBLOCKS, NTHREADS, SMEM_BYTES>>>(x, ld0, b1, b2, b3, T, out);
}

// round 3
// speedup vs baseline: 1.8826x; 1.8826x over previous
#include <cuda_runtime.h>
#include <cstdint>

// ---------------------------------------------------------------------------
// CNF Dopri5 fixed-step solver, fused persistent kernel, occupancy-tuned.
// B=8192, D=64, H=256, 10 steps x 6 stages. 32 samples/block, 256 blocks,
// 2 CTAs/SM co-resident (smem ~90KB, regs capped at 128).
// ---------------------------------------------------------------------------

#define DB 64
#define HB 256
#define BT 8192
#define NSTEPS 10
#define SB 32            // samples per block
#define SP 36            // padded row length in smem (floats)
#define NTHREADS 256
#define NBLOCKS (BT / SB)   // 256

// Global scratch (static __device__; no cudaMalloc).
__device__ float g_W1t[DB * HB];        // [d][h]  = W1[h][d]
__device__ float g_W2t[HB * HB];        // [i][j]  = W2[j][i]
__device__ float g_Et [HB * HB];        // [i][j]  = W2[j][i] * G[i][j],  G = W1 @ W3
__device__ float g_W3t[HB * DB];        // [j][d]  = W3[d][j]
__device__ float g_k[5][BT * DB];       // k1..k5, [stage][s][d]

__constant__ float c_A[6][6] = {
    { 0.2f, 0.f, 0.f, 0.f, 0.f, 0.f },
    { 3.f/40.f, 9.f/40.f, 0.f, 0.f, 0.f, 0.f },
    { 44.f/45.f, -56.f/15.f, 32.f/9.f, 0.f, 0.f, 0.f },
    { 19372.f/6561.f, -25360.f/2187.f, 64448.f/6561.f, -212.f/729.f, 0.f, 0.f },
    { 9017.f/3168.f, -355.f/33.f, 46732.f/5247.f, 49.f/176.f, -5103.f/18656.f, 0.f },
    { 35.f/384.f, 0.f, 500.f/1113.f, 125.f/192.f, -2187.f/6784.f, 11.f/84.f }
};
__constant__ float c_CL[6] = {
    35.f/384.f, 0.f, 500.f/1113.f, 125.f/192.f, -2187.f/6784.f, 11.f/84.f
};

__device__ __forceinline__ float softplusf(float z) {
    return fmaxf(z, 0.f) + log1pf(__expf(-fabsf(z)));
}
__device__ __forceinline__ float sigm(float z) {
    return 1.f / (1.f + __expf(-z));
}

// ---------------------------------------------------------------------------
// Prep: transposed weights + trace matrix E. grid=(HB), block=(HB).
// ---------------------------------------------------------------------------
__global__ void cnf_prep_kernel(const float* __restrict__ W1,
                                const float* __restrict__ W2,
                                const float* __restrict__ W3) {
    int i = blockIdx.x;
    int j = threadIdx.x;
    float g = 0.f;
    #pragma unroll
    for (int d = 0; d < DB; ++d)
        g += W1[i * DB + d] * W3[d * HB + j];
    float w2 = W2[j * HB + i];
    g_W2t[i * HB + j] = w2;
    g_Et [i * HB + j] = w2 * g;
    if (i < DB) g_W1t[i * HB + j] = W1[j * DB + i];
    if (j < DB) g_W3t[i * DB + j] = W3[j * HB + i];
}

// Macro params named to avoid .x/.y/.z/.w token capture.
#define FMA4I(Aarr, boff, wscal, vvec) \
    { Aarr[(boff)+0] += (wscal)*(vvec).x; Aarr[(boff)+1] += (wscal)*(vvec).y; \
      Aarr[(boff)+2] += (wscal)*(vvec).z; Aarr[(boff)+3] += (wscal)*(vvec).w; }

// ---------------------------------------------------------------------------
// Main fused solver. grid=256, block=256, dyn smem ~90KB, 2 CTAs/SM.
// ---------------------------------------------------------------------------
__global__ void __launch_bounds__(NTHREADS, 2)
cnf_main_kernel(const float* __restrict__ x,
                const float* __restrict__ ld0,
                const float* __restrict__ b1,
                const float* __restrict__ b2,
                const float* __restrict__ b3,
                const float* __restrict__ Tptr,
                float* __restrict__ out) {
    extern __shared__ float sm[];
    float* yt  = sm;                    // [DB][SP]
    float* yst = yt  + DB * SP;         // [DB][SP]
    float* h1t = yst + DB * SP;         // [HB][SP]
    float* s1t = h1t + HB * SP;         // [HB][SP]
    float* trs = s1t + HB * SP;         // [SB]
    float* lds = trs + SB;              // [SB]
    float* h2t = h1t;                   // alias

    const int tid   = threadIdx.x;
    const int gbase = blockIdx.x * SB;

    // phase C / io mapping: 8 samples per thread
    const int d  = tid & 63;
    const int sg = tid >> 6;            // 0..3
    const int sbase = sg * 8;

    // phase A mapping: 2 h rows x 16 samples
    const int hpair = (tid & 127) * 2;
    const int soff  = (tid >> 7) * 16;  // 0 or 16

    // phase B mapping: 8 j x 4 s
    const int j0  = (tid >> 3) * 8;     // 0..248
    const int ssb = (tid & 7) * 4;      // 0..28

    const float dt = Tptr[0] * (1.0f / NSTEPS);

    #pragma unroll
    for (int c = 0; c < 8; ++c)
        yt[d * SP + sbase + c] = x[(gbase + sbase + c) * DB + d];
    if (tid < SB) lds[tid] = ld0[gbase + tid];

    for (int step = 0; step < NSTEPS; ++step) {
        #pragma unroll
        for (int c = 0; c < 8; ++c)
            yst[d * SP + sbase + c] = yt[d * SP + sbase + c];

        for (int st = 0; st < 6; ++st) {
            __syncthreads();   // yst ready

            // ============== Phase A: z1 = W1 y + b1 -> h1, s1 ==============
            float accA[32];
            #pragma unroll
            for (int i = 0; i < 32; ++i) accA[i] = 0.f;
            #pragma unroll 4
            for (int dd = 0; dd < DB; ++dd) {
                float2 wv = *(const float2*)&g_W1t[dd * HB + hpair];
                #pragma unroll
                for (int q = 0; q < 4; ++q) {
                    float4 yv = *(const float4*)&yst[dd * SP + soff + q * 4];
                    FMA4I(accA, q * 4,      wv.x, yv);
                    FMA4I(accA, 16 + q * 4, wv.y, yv);
                }
            }
            {
                float bv0 = b1[hpair], bv1 = b1[hpair + 1];
                #pragma unroll
                for (int q = 0; q < 4; ++q) {
                    float z0 = accA[q*4+0] + bv0, z1 = accA[q*4+1] + bv0;
                    float z2 = accA[q*4+2] + bv0, z3 = accA[q*4+3] + bv0;
                    *(float4*)&h1t[hpair * SP + soff + q*4] =
                        make_float4(softplusf(z0), softplusf(z1), softplusf(z2), softplusf(z3));
                    *(float4*)&s1t[hpair * SP + soff + q*4] =
                        make_float4(sigm(z0), sigm(z1), sigm(z2), sigm(z3));
                    float u0 = accA[16+q*4+0] + bv1, u1 = accA[16+q*4+1] + bv1;
                    float u2 = accA[16+q*4+2] + bv1, u3 = accA[16+q*4+3] + bv1;
                    *(float4*)&h1t[(hpair+1) * SP + soff + q*4] =
                        make_float4(softplusf(u0), softplusf(u1), softplusf(u2), softplusf(u3));
                    *(float4*)&s1t[(hpair+1) * SP + soff + q*4] =
                        make_float4(sigm(u0), sigm(u1), sigm(u2), sigm(u3));
                }
            }
            if (tid < SB) trs[tid] = 0.f;
            __syncthreads();   // h1/s1 + zeroed trs visible

            // ====== Phase B: z2 = W2 h1 + b2, t = E s1, trace, h2 ==========
            float az[32], at_[32];
            #pragma unroll
            for (int i = 0; i < 32; ++i) { az[i] = 0.f; at_[i] = 0.f; }
            {
                const float* w2p = &g_W2t[j0];
                const float* etp = &g_Et [j0];
                #pragma unroll 2
                for (int k = 0; k < HB; ++k) {
                    float4 hv = *(const float4*)&h1t[k * SP + ssb];
                    float4 sv = *(const float4*)&s1t[k * SP + ssb];
                    float4 w2a = *(const float4*)(w2p + k * HB);
                    float4 w2b = *(const float4*)(w2p + k * HB + 4);
                    float4 eva = *(const float4*)(etp + k * HB);
                    float4 evb = *(const float4*)(etp + k * HB + 4);
                    FMA4I(az,  0,  w2a.x, hv); FMA4I(az,  4,  w2a.y, hv);
                    FMA4I(az,  8,  w2a.z, hv); FMA4I(az, 12,  w2a.w, hv);
                    FMA4I(az, 16,  w2b.x, hv); FMA4I(az, 20,  w2b.y, hv);
                    FMA4I(az, 24,  w2b.z, hv); FMA4I(az, 28,  w2b.w, hv);
                    FMA4I(at_, 0,  eva.x, sv); FMA4I(at_, 4,  eva.y, sv);
                    FMA4I(at_, 8,  eva.z, sv); FMA4I(at_, 12, eva.w, sv);
                    FMA4I(at_, 16, evb.x, sv); FMA4I(at_, 20, evb.y, sv);
                    FMA4I(at_, 24, evb.z, sv); FMA4I(at_, 28, evb.w, sv);
                }
            }
            float trp[4] = {0.f, 0.f, 0.f, 0.f};
            float h2keep[32];
            #pragma unroll
            for (int a = 0; a < 8; ++a) {
                float bb = b2[j0 + a];
                #pragma unroll
                for (int q = 0; q < 4; ++q) {
                    float z = az[a*4+q] + bb;
                    h2keep[a*4 + q] = softplusf(z);
                    trp[q] += sigm(z) * at_[a*4+q];
                }
            }
            // in-warp partial reduce over j-groups sharing ssb (lanes +8, +16, +24)
            #pragma unroll
            for (int q = 0; q < 4; ++q) {
                trp[q] += __shfl_down_sync(0xFFFFFFFFu, trp[q], 16);
                trp[q] += __shfl_down_sync(0xFFFFFFFFu, trp[q], 8);
            }
            if ((tid & 31) < 8) {
                #pragma unroll
                for (int q = 0; q < 4; ++q) atomicAdd(&trs[ssb + q], trp[q]);
            }
            __syncthreads();   // h1t/s1t free; trs final

            if (tid < SB) lds[tid] += dt * c_CL[st] * trs[tid];

            #pragma unroll
            for (int a = 0; a < 8; ++a)
                *(float4*)&h2t[(j0 + a) * SP + ssb] =
                    make_float4(h2keep[a*4+0], h2keep[a*4+1],
                                h2keep[a*4+2], h2keep[a*4+3]);
            __syncthreads();   // h2t ready

            // ====== Phase C: dy = W3 h2 + b3, store k, stage combine =======
            float acc[8];
            #pragma unroll
            for (int c = 0; c < 8; ++c) acc[c] = 0.f;
            #pragma unroll 4
            for (int j = 0; j < HB; ++j) {
                float w3s = g_W3t[j * DB + d];
                float4 hv0 = *(const float4*)&h2t[j * SP + sbase];
                float4 hv1 = *(const float4*)&h2t[j * SP + sbase + 4];
                FMA4I(acc, 0, w3s, hv0);
                FMA4I(acc, 4, w3s, hv1);
            }
            {
                float b3v = b3[d];
                #pragma unroll
                for (int c = 0; c < 8; ++c) acc[c] += b3v;
            }
            if (st < 5) {
                #pragma unroll
                for (int c = 0; c < 8; ++c)
                    g_k[st][(gbase + sbase + c) * DB + d] = acc[c];
            }
            {
                float alast = c_A[st][st];
                #pragma unroll
                for (int c = 0; c < 8; ++c) {
                    int s = sbase + c;
                    float v = alast * acc[c];
                    for (int m = 0; m < st; ++m)
                        v += c_A[st][m] * g_k[m][(gbase + s) * DB + d];
                    v = yt[d * SP + s] + dt * v;
                    if (st < 5) yst[d * SP + s] = v;
                    else        yt [d * SP + s] = v;
                }
            }
        } // stages
    } // steps

    __syncthreads();
    #pragma unroll
    for (int c = 0; c < 8; ++c)
        out[(gbase + sbase + c) * DB + d] = yt[d * SP + sbase + c];
    if (tid < SB) out[BT * DB + gbase + tid] = lds[tid];
}

// ---------------------------------------------------------------------------
#define SMEM_BYTES ((2 * DB * SP + 2 * HB * SP + 2 * SB) * 4)

extern "C" void kernel_launch(void* const* d_in, const int* in_sizes, int n_in,
                              void* d_out, int out_size) {
    const float* x   = (const float*)d_in[0];
    const float* ld0 = (const float*)d_in[1];
    const float* W1  = (const float*)d_in[2];
    const float* b1  = (const float*)d_in[3];
    const float* W2  = (const float*)d_in[4];
    const float* b2  = (const float*)d_in[5];
    const float* W3  = (const float*)d_in[6];
    const float* b3  = (const float*)d_in[7];
    const float* T   = (const float*)d_in[8];
    float* out = (float*)d_out;

    cudaFuncSetAttribute(cnf_main_kernel,
                         cudaFuncAttributeMaxDynamicSharedMemorySize, SMEM_BYTES);

    cnf_prep_kernel<<<HB, HB>>>(W1, W2, W3);
    cnf_main_kernel<<<NBLOCKS, NTHREADS, SMEM_BYTES>>>(x, ld0, b1, b2, b3, T, out);
}

// round 4
// speedup vs baseline: 2.5314x; 1.3446x over previous
#include <cuda_runtime.h>
#include <cuda_bf16.h>
#include <cstdint>

// ---------------------------------------------------------------------------
// CNF Dopri5 solver with tensor-core (mma.sync bf16, 3-pass hi/lo split) GEMMs.
// B=8192, D=64, H=256, 10 steps x 6 stages. 64 samples/CTA, 128 CTAs,
// 512 threads (16 warps). Activations bf16 hi/lo in SMEM; weights bf16 hi/lo
// in global (L2-resident), fragment-loaded per stage. fp32 accumulate.
// ---------------------------------------------------------------------------

#define DB 64
#define HB 256
#define BT 8192
#define NSTEPS 10
#define SB 64
#define NTHREADS 512
#define NBLOCKS (BT / SB)      // 128

#define LDH 264                // padded k-row for h arrays [64][264] (bf16)
#define LDY 72                 // padded k-row for yst arrays [64][72]
#define LDF 68                 // padded row for fp32 y [64][68]

typedef __nv_bfloat16 bf16;

// Weights, split hi/lo bf16 (prep kernel writes these once per launch).
__device__ bf16 g_W1h[HB * DB], g_W1l[HB * DB];     // [h][d]
__device__ bf16 g_W2h[HB * HB], g_W2l[HB * HB];     // [j][i]
__device__ bf16 g_Eh [HB * HB], g_El [HB * HB];     // [j][i] = W2[j][i]*G[i][j]
__device__ bf16 g_W3h[DB * HB], g_W3l[DB * HB];     // [d][j]
__device__ float g_k[5][BT * DB];                   // k1..k5 fp32 [stage][s][d]

__constant__ float c_A[6][6] = {
    { 0.2f, 0.f, 0.f, 0.f, 0.f, 0.f },
    { 3.f/40.f, 9.f/40.f, 0.f, 0.f, 0.f, 0.f },
    { 44.f/45.f, -56.f/15.f, 32.f/9.f, 0.f, 0.f, 0.f },
    { 19372.f/6561.f, -25360.f/2187.f, 64448.f/6561.f, -212.f/729.f, 0.f, 0.f },
    { 9017.f/3168.f, -355.f/33.f, 46732.f/5247.f, 49.f/176.f, -5103.f/18656.f, 0.f },
    { 35.f/384.f, 0.f, 500.f/1113.f, 125.f/192.f, -2187.f/6784.f, 11.f/84.f }
};
__constant__ float c_CL[6] = {
    35.f/384.f, 0.f, 500.f/1113.f, 125.f/192.f, -2187.f/6784.f, 11.f/84.f
};

__device__ __forceinline__ uint32_t ld32(const bf16* p) {
    return *reinterpret_cast<const uint32_t*>(p);
}
__device__ __forceinline__ void bsplit(float v, bf16& hi, bf16& lo) {
    hi = __float2bfloat16(v);
    lo = __float2bfloat16(v - __bfloat162float(hi));
}

#define MMA16816(dd, aa, bb0, bb1) \
    asm volatile("mma.sync.aligned.m16n8k16.row.col.f32.bf16.bf16.f32 " \
        "{%0,%1,%2,%3}, {%4,%5,%6,%7}, {%8,%9}, {%0,%1,%2,%3};" \
        : "+f"(dd[0]), "+f"(dd[1]), "+f"(dd[2]), "+f"(dd[3]) \
        : "r"(aa[0]), "r"(aa[1]), "r"(aa[2]), "r"(aa[3]), "r"(bb0), "r"(bb1))

// A-fragment (m16k16) from row-major bf16 [m][ldw], rows r0/r0+8, k-offset k0.
__device__ __forceinline__ void load_afrag(const bf16* W, int ldw, int r0, int k0,
                                           uint32_t a[4]) {
    const bf16* p0 = W + r0 * ldw + k0;
    const bf16* p1 = W + (r0 + 8) * ldw + k0;
    a[0] = ld32(p0); a[1] = ld32(p1); a[2] = ld32(p0 + 8); a[3] = ld32(p1 + 8);
}

// ---------------------------------------------------------------------------
// Prep: split weights into bf16 hi/lo; build E = W2 .* G^T, G = W1 @ W3.
// grid=(HB), block=(HB).
// ---------------------------------------------------------------------------
__global__ void cnf_prep_kernel(const float* __restrict__ W1,
                                const float* __restrict__ W2,
                                const float* __restrict__ W3) {
    int i = blockIdx.x;    // 0..255
    int j = threadIdx.x;   // 0..255
    float g = 0.f;
    #pragma unroll
    for (int d = 0; d < DB; ++d)
        g += W1[i * DB + d] * W3[d * HB + j];       // G[i][j]
    float ev = W2[j * HB + i] * g;                  // E[j][i]
    bsplit(ev, g_Eh[j * HB + i], g_El[j * HB + i]);
    bsplit(W2[i * HB + j], g_W2h[i * HB + j], g_W2l[i * HB + j]);
    if (j < DB) bsplit(W1[i * DB + j], g_W1h[i * DB + j], g_W1l[i * DB + j]);
    if (i < DB) bsplit(W3[i * HB + j], g_W3h[i * HB + j], g_W3l[i * HB + j]);
}

// ---------------------------------------------------------------------------
// Main solver. grid=128, block=512, dyn smem ~172KB.
// ---------------------------------------------------------------------------
__global__ void __launch_bounds__(NTHREADS, 1)
cnf_main_kernel(const float* __restrict__ x,
                const float* __restrict__ ld0,
                const float* __restrict__ b1g,
                const float* __restrict__ b2g,
                const float* __restrict__ b3g,
                const float* __restrict__ Tptr,
                float* __restrict__ out) {
    extern __shared__ char smraw[];
    bf16* h1h = (bf16*)smraw;            // [64][LDH]  h1 hi   (h2 hi after phase B)
    bf16* h1l = h1h + SB * LDH;          // [64][LDH]  h1 lo
    bf16* s1h = h1l + SB * LDH;          // [64][LDH]  s1 hi
    bf16* s1l = s1h + SB * LDH;          // [64][LDH]  s1 lo
    bf16* ysh = s1l + SB * LDH;          // [64][LDY]  yst hi
    bf16* ysl = ysh + SB * LDY;          // [64][LDY]  yst lo
    float* yt = (float*)(ysl + SB * LDY);// [64][LDF]  master y fp32
    float* trs = yt + SB * LDF;          // [64]
    float* lds = trs + SB;               // [64]

    const int tid  = threadIdx.x;
    const int lane = tid & 31;
    const int w    = tid >> 5;           // warp 0..15
    const int qrow = lane >> 2;          // 0..7
    const int qcol = lane & 3;           // 0..3
    const int gbase = blockIdx.x * SB;

    const float dt = Tptr[0] * (1.0f / NSTEPS);

    // ---- init: y fp32 + yst hi/lo, logdet ----
    {
        const int d = tid & 63;
        const int srow = tid >> 6;       // 0..7, 8 samples each
        #pragma unroll
        for (int c = 0; c < 8; ++c) {
            int s = srow * 8 + c;
            float v = x[(gbase + s) * DB + d];
            yt[s * LDF + d] = v;
            bsplit(v, ysh[s * LDY + d], ysl[s * LDY + d]);
        }
        if (tid < SB) lds[tid] = ld0[gbase + tid];
    }

    for (int step = 0; step < NSTEPS; ++step) {
        for (int st = 0; st < 6; ++st) {
            __syncthreads();                    // (1) yst ready
            if (tid < SB) trs[tid] = 0.f;

            // ================= Phase A: z1 = W1 yst + b1 =================
            {
                float acc[8][4];
                #pragma unroll
                for (int nt = 0; nt < 8; ++nt)
                    #pragma unroll
                    for (int e = 0; e < 4; ++e) acc[nt][e] = 0.f;

                const bf16* WA[3] = { g_W1h, g_W1h, g_W1l };
                const bf16* BA[3] = { ysh,   ysl,   ysh   };
                #pragma unroll 1
                for (int p = 0; p < 3; ++p) {
                    const bf16* Wp = WA[p];
                    const bf16* Bp = BA[p];
                    #pragma unroll
                    for (int kc = 0; kc < 4; ++kc) {
                        int k0 = kc * 16 + 2 * qcol;
                        uint32_t a[4];
                        load_afrag(Wp, DB, 16 * w + qrow, k0, a);
                        #pragma unroll
                        for (int nt = 0; nt < 8; ++nt) {
                            const bf16* bp = Bp + (nt * 8 + qrow) * LDY + k0;
                            uint32_t bb0 = ld32(bp), bb1 = ld32(bp + 8);
                            MMA16816(acc[nt], a, bb0, bb1);
                        }
                    }
                }
                // epilogue: softplus/sigmoid, split, store h1/s1
                float bm0 = b1g[16 * w + qrow], bm1 = b1g[16 * w + qrow + 8];
                #pragma unroll
                for (int nt = 0; nt < 8; ++nt) {
                    #pragma unroll
                    for (int e = 0; e < 4; ++e) {
                        int m = 16 * w + qrow + ((e >> 1) << 3);
                        int n = nt * 8 + 2 * qcol + (e & 1);
                        float z = acc[nt][e] + ((e >> 1) ? bm1 : bm0);
                        float t = __expf(-fabsf(z));
                        float u = __fdividef(1.f, 1.f + t);
                        float sp = fmaxf(z, 0.f) + __logf(1.f + t);
                        float sg = (z > 0.f) ? u : 1.f - u;
                        bsplit(sp, h1h[n * LDH + m], h1l[n * LDH + m]);
                        bsplit(sg, s1h[n * LDH + m], s1l[n * LDH + m]);
                    }
                }
            }
            __syncthreads();                    // (3) h1/s1 ready

            // ===== Phase B: z2 = W2 h1 + b2 ; t = E s1 ; trace; h2 =======
            float accZ[8][4], accT[8][4];
            {
                #pragma unroll
                for (int nt = 0; nt < 8; ++nt)
                    #pragma unroll
                    for (int e = 0; e < 4; ++e) { accZ[nt][e] = 0.f; accT[nt][e] = 0.f; }

                const bf16* WZ[3] = { g_W2h, g_W2h, g_W2l };
                const bf16* BZ[3] = { h1h,   h1l,   h1h   };
                #pragma unroll 1
                for (int p = 0; p < 3; ++p) {
                    const bf16* Wp = WZ[p];
                    const bf16* Bp = BZ[p];
                    #pragma unroll 2
                    for (int kc = 0; kc < 16; ++kc) {
                        int k0 = kc * 16 + 2 * qcol;
                        uint32_t a[4];
                        load_afrag(Wp, HB, 16 * w + qrow, k0, a);
                        #pragma unroll
                        for (int nt = 0; nt < 8; ++nt) {
                            const bf16* bp = Bp + (nt * 8 + qrow) * LDH + k0;
                            uint32_t bb0 = ld32(bp), bb1 = ld32(bp + 8);
                            MMA16816(accZ[nt], a, bb0, bb1);
                        }
                    }
                }
                const bf16* WT[3] = { g_Eh, g_Eh, g_El };
                const bf16* BT3[3] = { s1h, s1l, s1h };
                #pragma unroll 1
                for (int p = 0; p < 3; ++p) {
                    const bf16* Wp = WT[p];
                    const bf16* Bp = BT3[p];
                    #pragma unroll 2
                    for (int kc = 0; kc < 16; ++kc) {
                        int k0 = kc * 16 + 2 * qcol;
                        uint32_t a[4];
                        load_afrag(Wp, HB, 16 * w + qrow, k0, a);
                        #pragma unroll
                        for (int nt = 0; nt < 8; ++nt) {
                            const bf16* bp = Bp + (nt * 8 + qrow) * LDH + k0;
                            uint32_t bb0 = ld32(bp), bb1 = ld32(bp + 8);
                            MMA16816(accT[nt], a, bb0, bb1);
                        }
                    }
                }
            }
            __syncthreads();                    // (5) all h1/s1 reads done

            // epilogue B: h2 = softplus(z2) over h1 arrays; trace partials
            {
                float bm0 = b2g[16 * w + qrow], bm1 = b2g[16 * w + qrow + 8];
                #pragma unroll
                for (int nt = 0; nt < 8; ++nt) {
                    float p0 = 0.f, p1 = 0.f;   // per-n trace partials
                    #pragma unroll
                    for (int e = 0; e < 4; ++e) {
                        int m = 16 * w + qrow + ((e >> 1) << 3);
                        int n = nt * 8 + 2 * qcol + (e & 1);
                        float z = accZ[nt][e] + ((e >> 1) ? bm1 : bm0);
                        float t = __expf(-fabsf(z));
                        float u = __fdividef(1.f, 1.f + t);
                        float sp = fmaxf(z, 0.f) + __logf(1.f + t);
                        float sg = (z > 0.f) ? u : 1.f - u;
                        bsplit(sp, h1h[n * LDH + m], h1l[n * LDH + m]);
                        float contrib = sg * accT[nt][e];
                        if (e & 1) p1 += contrib; else p0 += contrib;
                    }
                    // reduce over lanes with same qcol (xor 4, 8, 16)
                    #pragma unroll
                    for (int msk = 4; msk <= 16; msk <<= 1) {
                        p0 += __shfl_xor_sync(0xFFFFFFFFu, p0, msk);
                        p1 += __shfl_xor_sync(0xFFFFFFFFu, p1, msk);
                    }
                    if (qrow == 0) {
                        atomicAdd(&trs[nt * 8 + 2 * qcol], p0);
                        atomicAdd(&trs[nt * 8 + 2 * qcol + 1], p1);
                    }
                }
            }
            __syncthreads();                    // (6) h2 + trs ready

            if (tid < SB) lds[tid] += dt * c_CL[st] * trs[tid];

            // ===== Phase C: dy = W3 h2 + b3 ; k store; stage combine ======
            {
                const int mt = w & 3;           // m-tile (D rows 16mt..)
                const int np = w >> 2;          // n-pair (n-tiles 2np, 2np+1)
                float acc[2][4];
                #pragma unroll
                for (int f = 0; f < 2; ++f)
                    #pragma unroll
                    for (int e = 0; e < 4; ++e) acc[f][e] = 0.f;

                const bf16* WC[3] = { g_W3h, g_W3h, g_W3l };
                const bf16* BC[3] = { h1h,   h1l,   h1h   };
                #pragma unroll 1
                for (int p = 0; p < 3; ++p) {
                    const bf16* Wp = WC[p];
                    const bf16* Bp = BC[p];
                    #pragma unroll 4
                    for (int kc = 0; kc < 16; ++kc) {
                        int k0 = kc * 16 + 2 * qcol;
                        uint32_t a[4];
                        load_afrag(Wp, HB, 16 * mt + qrow, k0, a);
                        #pragma unroll
                        for (int f = 0; f < 2; ++f) {
                            const bf16* bp = Bp + ((2 * np + f) * 8 + qrow) * LDH + k0;
                            uint32_t bb0 = ld32(bp), bb1 = ld32(bp + 8);
                            MMA16816(acc[f], a, bb0, bb1);
                        }
                    }
                }
                // epilogue: bias, store k, Dopri5 combine, write yst (and y)
                float bm0 = b3g[16 * mt + qrow], bm1 = b3g[16 * mt + qrow + 8];
                float alast = c_A[st][st];
                #pragma unroll
                for (int f = 0; f < 2; ++f) {
                    #pragma unroll
                    for (int e = 0; e < 4; ++e) {
                        int dd = 16 * mt + qrow + ((e >> 1) << 3);
                        int s  = (2 * np + f) * 8 + 2 * qcol + (e & 1);
                        float v = acc[f][e] + ((e >> 1) ? bm1 : bm0);   // dy
                        int gidx = (gbase + s) * DB + dd;
                        if (st < 5) g_k[st][gidx] = v;
                        float comb = alast * v;
                        for (int m = 0; m < st; ++m)
                            comb += c_A[st][m] * g_k[m][gidx];
                        float nv = yt[s * LDF + dd] + dt * comb;
                        if (st == 5) yt[s * LDF + dd] = nv;
                        bsplit(nv, ysh[s * LDY + dd], ysl[s * LDY + dd]);
                    }
                }
            }
        } // stages
    } // steps

    __syncthreads();
    // ---- output ----
    {
        const int d = tid & 63;
        const int srow = tid >> 6;
        #pragma unroll
        for (int c = 0; c < 8; ++c) {
            int s = srow * 8 + c;
            out[(gbase + s) * DB + d] = yt[s * LDF + d];
        }
        if (tid < SB) out[BT * DB + gbase + tid] = lds[tid];
    }
}

// ---------------------------------------------------------------------------
#define SMEM_BYTES ((4 * SB * LDH + 2 * SB * LDY) * 2 + (SB * LDF + 2 * SB) * 4)

extern "C" void kernel_launch(void* const* d_in, const int* in_sizes, int n_in,
                              void* d_out, int out_size) {
    const float* x   = (const float*)d_in[0];
    const float* ld0 = (const float*)d_in[1];
    const float* W1  = (const float*)d_in[2];
    const float* b1  = (const float*)d_in[3];
    const float* W2  = (const float*)d_in[4];
    const float* b2  = (const float*)d_in[5];
    const float* W3  = (const float*)d_in[6];
    const float* b3  = (const float*)d_in[7];
    const float* T   = (const float*)d_in[8];
    float* out = (float*)d_out;

    cudaFuncSetAttribute(cnf_main_kernel,
                         cudaFuncAttributeMaxDynamicSharedMemorySize, SMEM_BYTES);

    cnf_prep_kernel<<<HB, HB>>>(W1, W2, W3);
    cnf_main_kernel<<<NBLOCKS, NTHREADS, SMEM_BYTES>>>(x, ld0, b1, b2, b3, T, out);
}

// round 5
// speedup vs baseline: 6.1399x; 2.4255x over previous
#include <cuda_runtime.h>
#include <cuda_bf16.h>
#include <cstdint>

// ---------------------------------------------------------------------------
// CNF Dopri5 solver, tensor-core bf16 hi/lo 3-pass GEMMs.
// R5: ldmatrix B-fragments, B-reuse across passes, fragment-packed A weights.
// B=8192, D=64, H=256, 10 steps x 6 stages. 64 samples/CTA, 128 CTAs, 512 thr.
// ---------------------------------------------------------------------------

#define DB 64
#define HB 256
#define BT 8192
#define NSTEPS 10
#define SB 64
#define NTHREADS 512
#define NBLOCKS (BT / SB)      // 128

#define LDH 264                // padded k-row for h arrays (bf16) ; 528B rows, 16B-aligned
#define LDY 72                 // padded k-row for yst arrays    ; 144B rows, 16B-aligned
#define LDF 68                 // padded row for fp32 y

typedef __nv_bfloat16 bf16;

// Fragment-packed weights (A-operand order): uint4 index = (mtile*KC+kc)*32+lane.
__device__ __align__(16) bf16 g_W1hf[HB * DB], g_W1lf[HB * DB];     // M=256,K=64 (KC=4)
__device__ __align__(16) bf16 g_W2hf[HB * HB], g_W2lf[HB * HB];     // M=256,K=256 (KC=16)
__device__ __align__(16) bf16 g_Ehf [HB * HB], g_Elf [HB * HB];     // M=256,K=256
__device__ __align__(16) bf16 g_W3hf[DB * HB], g_W3lf[DB * HB];     // M=64, K=256
__device__ float g_k[5][BT * DB];                                   // k1..k5 fp32

__constant__ float c_A[6][6] = {
    { 0.2f, 0.f, 0.f, 0.f, 0.f, 0.f },
    { 3.f/40.f, 9.f/40.f, 0.f, 0.f, 0.f, 0.f },
    { 44.f/45.f, -56.f/15.f, 32.f/9.f, 0.f, 0.f, 0.f },
    { 19372.f/6561.f, -25360.f/2187.f, 64448.f/6561.f, -212.f/729.f, 0.f, 0.f },
    { 9017.f/3168.f, -355.f/33.f, 46732.f/5247.f, 49.f/176.f, -5103.f/18656.f, 0.f },
    { 35.f/384.f, 0.f, 500.f/1113.f, 125.f/192.f, -2187.f/6784.f, 11.f/84.f }
};
__constant__ float c_CL[6] = {
    35.f/384.f, 0.f, 500.f/1113.f, 125.f/192.f, -2187.f/6784.f, 11.f/84.f
};

__device__ __forceinline__ void bsplit(float v, bf16& hi, bf16& lo) {
    hi = __float2bfloat16(v);
    lo = __float2bfloat16(v - __bfloat162float(hi));
}

// Packed-fragment element index for A element (m,k) of a matrix with KC k-tiles.
__device__ __forceinline__ int pidx(int m, int k, int KC) {
    int mtile = m >> 4;
    int kc    = k >> 4;
    int lane  = (m & 7) * 4 + ((k & 7) >> 1);
    int reg   = ((k >> 3) & 1) * 2 + ((m >> 3) & 1);
    int half  = k & 1;
    return (((mtile * KC + kc) * 32 + lane) * 4 + reg) * 2 + half;
}

#define MMA16816(dd, a0, a1, a2, a3, bb0, bb1) \
    asm volatile("mma.sync.aligned.m16n8k16.row.col.f32.bf16.bf16.f32 " \
        "{%0,%1,%2,%3}, {%4,%5,%6,%7}, {%8,%9}, {%0,%1,%2,%3};" \
        : "+f"(dd[0]), "+f"(dd[1]), "+f"(dd[2]), "+f"(dd[3]) \
        : "r"(a0), "r"(a1), "r"(a2), "r"(a3), "r"(bb0), "r"(bb1))

// ldmatrix.x4: B-fragments for two adjacent n-tiles (nt0, nt0+1) at k-offset k0c.
// r[0]=bb0(nt0) r[1]=bb1(nt0) r[2]=bb0(nt0+1) r[3]=bb1(nt0+1)
__device__ __forceinline__ void ldsm_b(uint32_t r[4], const bf16* base,
                                       int nrow0, int ld, int k0c, int lane) {
    int mat = lane >> 3, rr = lane & 7;
    const bf16* p = base + (nrow0 + ((mat >> 1) << 3) + rr) * ld
                         + k0c + ((mat & 1) << 3);
    uint32_t saddr = (uint32_t)__cvta_generic_to_shared(p);
    asm volatile("ldmatrix.sync.aligned.m8n8.x4.shared.b16 {%0,%1,%2,%3}, [%4];"
        : "=r"(r[0]), "=r"(r[1]), "=r"(r[2]), "=r"(r[3]) : "r"(saddr));
}

__device__ __forceinline__ void ldfrag(const bf16* packed, int mtile, int KC,
                                       int kc, int lane, uint32_t a[4]) {
    uint4 v = ((const uint4*)packed)[(mtile * KC + kc) * 32 + lane];
    a[0] = v.x; a[1] = v.y; a[2] = v.z; a[3] = v.w;
}

// ---------------------------------------------------------------------------
// Prep: split weights hi/lo into packed fragment layout; E = W2 .* G^T.
// grid=(HB), block=(HB).
// ---------------------------------------------------------------------------
__global__ void cnf_prep_kernel(const float* __restrict__ W1,
                                const float* __restrict__ W2,
                                const float* __restrict__ W3) {
    int i = blockIdx.x;    // 0..255
    int j = threadIdx.x;   // 0..255
    float g = 0.f;
    #pragma unroll
    for (int d = 0; d < DB; ++d)
        g += W1[i * DB + d] * W3[d * HB + j];       // G[i][j]
    // E[j][i] = W2[j][i] * G[i][j]  (A element row=j, col=i)
    {
        float ev = W2[j * HB + i] * g;
        int q = pidx(j, i, 16);
        bsplit(ev, g_Ehf[q], g_Elf[q]);
    }
    // W2 element (row=i, col=j)
    {
        int q = pidx(i, j, 16);
        bsplit(W2[i * HB + j], g_W2hf[q], g_W2lf[q]);
    }
    if (j < DB) {   // W1 element (row=i out of 256, col=j out of 64)
        int q = pidx(i, j, 4);
        bsplit(W1[i * DB + j], g_W1hf[q], g_W1lf[q]);
    }
    if (i < DB) {   // W3 element (row=i out of 64, col=j out of 256)
        int q = pidx(i, j, 16);
        bsplit(W3[i * HB + j], g_W3hf[q], g_W3lf[q]);
    }
}

// ---------------------------------------------------------------------------
// Main solver. grid=128, block=512, dyn smem ~168KB.
// ---------------------------------------------------------------------------
__global__ void __launch_bounds__(NTHREADS, 1)
cnf_main_kernel(const float* __restrict__ x,
                const float* __restrict__ ld0,
                const float* __restrict__ b1g,
                const float* __restrict__ b2g,
                const float* __restrict__ b3g,
                const float* __restrict__ Tptr,
                float* __restrict__ out) {
    extern __shared__ char smraw[];
    bf16* h1h = (bf16*)smraw;            // [64][LDH]  h1 hi  (becomes h2 hi)
    bf16* h1l = h1h + SB * LDH;
    bf16* s1h = h1l + SB * LDH;
    bf16* s1l = s1h + SB * LDH;
    bf16* ysh = s1l + SB * LDH;          // [64][LDY]
    bf16* ysl = ysh + SB * LDY;
    float* yt = (float*)(ysl + SB * LDY);// [64][LDF]
    float* trs = yt + SB * LDF;
    float* lds = trs + SB;

    const int tid  = threadIdx.x;
    const int lane = tid & 31;
    const int w    = tid >> 5;
    const int qrow = lane >> 2;
    const int qcol = lane & 3;
    const int gbase = blockIdx.x * SB;

    const float dt = Tptr[0] * (1.0f / NSTEPS);

    {
        const int d = tid & 63;
        const int srow = tid >> 6;
        #pragma unroll
        for (int c = 0; c < 8; ++c) {
            int s = srow * 8 + c;
            float v = x[(gbase + s) * DB + d];
            yt[s * LDF + d] = v;
            bsplit(v, ysh[s * LDY + d], ysl[s * LDY + d]);
        }
        if (tid < SB) lds[tid] = ld0[gbase + tid];
    }

    for (int step = 0; step < NSTEPS; ++step) {
        for (int st = 0; st < 6; ++st) {
            __syncthreads();                    // yst ready
            if (tid < SB) trs[tid] = 0.f;

            // ================= Phase A: z1 = W1 yst + b1 =================
            {
                float acc[8][4];
                #pragma unroll
                for (int nt = 0; nt < 8; ++nt)
                    #pragma unroll
                    for (int e = 0; e < 4; ++e) acc[nt][e] = 0.f;

                #pragma unroll
                for (int kc = 0; kc < 4; ++kc) {
                    int k0c = kc * 16;
                    uint32_t bh[16], bl[16];
                    #pragma unroll
                    for (int np = 0; np < 4; ++np) {
                        ldsm_b(&bh[np * 4], ysh, np * 16, LDY, k0c, lane);
                        ldsm_b(&bl[np * 4], ysl, np * 16, LDY, k0c, lane);
                    }
                    uint32_t ah[4], al[4];
                    ldfrag(g_W1hf, w, 4, kc, lane, ah);
                    ldfrag(g_W1lf, w, 4, kc, lane, al);
                    #pragma unroll
                    for (int nt = 0; nt < 8; ++nt) {
                        uint32_t b0 = bh[(nt >> 1) * 4 + (nt & 1) * 2];
                        uint32_t b1 = bh[(nt >> 1) * 4 + (nt & 1) * 2 + 1];
                        MMA16816(acc[nt], ah[0], ah[1], ah[2], ah[3], b0, b1);
                    }
                    #pragma unroll
                    for (int nt = 0; nt < 8; ++nt) {
                        uint32_t b0 = bl[(nt >> 1) * 4 + (nt & 1) * 2];
                        uint32_t b1 = bl[(nt >> 1) * 4 + (nt & 1) * 2 + 1];
                        MMA16816(acc[nt], ah[0], ah[1], ah[2], ah[3], b0, b1);
                    }
                    #pragma unroll
                    for (int nt = 0; nt < 8; ++nt) {
                        uint32_t b0 = bh[(nt >> 1) * 4 + (nt & 1) * 2];
                        uint32_t b1 = bh[(nt >> 1) * 4 + (nt & 1) * 2 + 1];
                        MMA16816(acc[nt], al[0], al[1], al[2], al[3], b0, b1);
                    }
                }
                // epilogue A
                float bm0 = b1g[16 * w + qrow], bm1 = b1g[16 * w + qrow + 8];
                #pragma unroll
                for (int nt = 0; nt < 8; ++nt) {
                    #pragma unroll
                    for (int e = 0; e < 4; ++e) {
                        int m = 16 * w + qrow + ((e >> 1) << 3);
                        int n = nt * 8 + 2 * qcol + (e & 1);
                        float z = acc[nt][e] + ((e >> 1) ? bm1 : bm0);
                        float t = __expf(-fabsf(z));
                        float u = __fdividef(1.f, 1.f + t);
                        float sp = fmaxf(z, 0.f) + __logf(1.f + t);
                        float sg = (z > 0.f) ? u : 1.f - u;
                        bsplit(sp, h1h[n * LDH + m], h1l[n * LDH + m]);
                        bsplit(sg, s1h[n * LDH + m], s1l[n * LDH + m]);
                    }
                }
            }
            __syncthreads();                    // h1/s1 ready

            // ===== Phase B: z2 = W2 h1 + b2 ; t = E s1 ; trace; h2 =======
            float accZ[8][4], accT[8][4];
            {
                #pragma unroll
                for (int nt = 0; nt < 8; ++nt)
                    #pragma unroll
                    for (int e = 0; e < 4; ++e) { accZ[nt][e] = 0.f; accT[nt][e] = 0.f; }

                // GEMM Z: W2 (hi/lo) x h1 (hi/lo)
                #pragma unroll 2
                for (int kc = 0; kc < 16; ++kc) {
                    int k0c = kc * 16;
                    uint32_t bh[16], bl[16];
                    #pragma unroll
                    for (int np = 0; np < 4; ++np) {
                        ldsm_b(&bh[np * 4], h1h, np * 16, LDH, k0c, lane);
                        ldsm_b(&bl[np * 4], h1l, np * 16, LDH, k0c, lane);
                    }
                    uint32_t ah[4], al[4];
                    ldfrag(g_W2hf, w, 16, kc, lane, ah);
                    ldfrag(g_W2lf, w, 16, kc, lane, al);
                    #pragma unroll
                    for (int nt = 0; nt < 8; ++nt) {
                        uint32_t b0 = bh[(nt >> 1) * 4 + (nt & 1) * 2];
                        uint32_t b1 = bh[(nt >> 1) * 4 + (nt & 1) * 2 + 1];
                        MMA16816(accZ[nt], ah[0], ah[1], ah[2], ah[3], b0, b1);
                    }
                    #pragma unroll
                    for (int nt = 0; nt < 8; ++nt) {
                        uint32_t b0 = bl[(nt >> 1) * 4 + (nt & 1) * 2];
                        uint32_t b1 = bl[(nt >> 1) * 4 + (nt & 1) * 2 + 1];
                        MMA16816(accZ[nt], ah[0], ah[1], ah[2], ah[3], b0, b1);
                    }
                    #pragma unroll
                    for (int nt = 0; nt < 8; ++nt) {
                        uint32_t b0 = bh[(nt >> 1) * 4 + (nt & 1) * 2];
                        uint32_t b1 = bh[(nt >> 1) * 4 + (nt & 1) * 2 + 1];
                        MMA16816(accZ[nt], al[0], al[1], al[2], al[3], b0, b1);
                    }
                }
                // GEMM T: E (hi/lo) x s1 (hi/lo)
                #pragma unroll 2
                for (int kc = 0; kc < 16; ++kc) {
                    int k0c = kc * 16;
                    uint32_t bh[16], bl[16];
                    #pragma unroll
                    for (int np = 0; np < 4; ++np) {
                        ldsm_b(&bh[np * 4], s1h, np * 16, LDH, k0c, lane);
                        ldsm_b(&bl[np * 4], s1l, np * 16, LDH, k0c, lane);
                    }
                    uint32_t ah[4], al[4];
                    ldfrag(g_Ehf, w, 16, kc, lane, ah);
                    ldfrag(g_Elf, w, 16, kc, lane, al);
                    #pragma unroll
                    for (int nt = 0; nt < 8; ++nt) {
                        uint32_t b0 = bh[(nt >> 1) * 4 + (nt & 1) * 2];
                        uint32_t b1 = bh[(nt >> 1) * 4 + (nt & 1) * 2 + 1];
                        MMA16816(accT[nt], ah[0], ah[1], ah[2], ah[3], b0, b1);
                    }
                    #pragma unroll
                    for (int nt = 0; nt < 8; ++nt) {
                        uint32_t b0 = bl[(nt >> 1) * 4 + (nt & 1) * 2];
                        uint32_t b1 = bl[(nt >> 1) * 4 + (nt & 1) * 2 + 1];
                        MMA16816(accT[nt], ah[0], ah[1], ah[2], ah[3], b0, b1);
                    }
                    #pragma unroll
                    for (int nt = 0; nt < 8; ++nt) {
                        uint32_t b0 = bh[(nt >> 1) * 4 + (nt & 1) * 2];
                        uint32_t b1 = bh[(nt >> 1) * 4 + (nt & 1) * 2 + 1];
                        MMA16816(accT[nt], al[0], al[1], al[2], al[3], b0, b1);
                    }
                }
            }
            __syncthreads();                    // all h1/s1 reads done

            // epilogue B: h2 = softplus(z2) into h1 arrays; trace partials
            {
                float bm0 = b2g[16 * w + qrow], bm1 = b2g[16 * w + qrow + 8];
                #pragma unroll
                for (int nt = 0; nt < 8; ++nt) {
                    float p0 = 0.f, p1 = 0.f;
                    #pragma unroll
                    for (int e = 0; e < 4; ++e) {
                        int m = 16 * w + qrow + ((e >> 1) << 3);
                        int n = nt * 8 + 2 * qcol + (e & 1);
                        float z = accZ[nt][e] + ((e >> 1) ? bm1 : bm0);
                        float t = __expf(-fabsf(z));
                        float u = __fdividef(1.f, 1.f + t);
                        float sp = fmaxf(z, 0.f) + __logf(1.f + t);
                        float sg = (z > 0.f) ? u : 1.f - u;
                        bsplit(sp, h1h[n * LDH + m], h1l[n * LDH + m]);
                        float contrib = sg * accT[nt][e];
                        if (e & 1) p1 += contrib; else p0 += contrib;
                    }
                    #pragma unroll
                    for (int msk = 4; msk <= 16; msk <<= 1) {
                        p0 += __shfl_xor_sync(0xFFFFFFFFu, p0, msk);
                        p1 += __shfl_xor_sync(0xFFFFFFFFu, p1, msk);
                    }
                    if (qrow == 0) {
                        atomicAdd(&trs[nt * 8 + 2 * qcol], p0);
                        atomicAdd(&trs[nt * 8 + 2 * qcol + 1], p1);
                    }
                }
            }
            __syncthreads();                    // h2 + trs ready

            if (tid < SB) lds[tid] += dt * c_CL[st] * trs[tid];

            // ===== Phase C: dy = W3 h2 + b3 ; k store; stage combine ======
            {
                const int mt = w & 3;           // m-tile over D=64
                const int np = w >> 2;          // n-pair
                float acc[2][4];
                #pragma unroll
                for (int f = 0; f < 2; ++f)
                    #pragma unroll
                    for (int e = 0; e < 4; ++e) acc[f][e] = 0.f;

                #pragma unroll 4
                for (int kc = 0; kc < 16; ++kc) {
                    int k0c = kc * 16;
                    uint32_t bh[4], bl[4];
                    ldsm_b(bh, h1h, np * 16, LDH, k0c, lane);
                    ldsm_b(bl, h1l, np * 16, LDH, k0c, lane);
                    uint32_t ah[4], al[4];
                    ldfrag(g_W3hf, mt, 16, kc, lane, ah);
                    ldfrag(g_W3lf, mt, 16, kc, lane, al);
                    MMA16816(acc[0], ah[0], ah[1], ah[2], ah[3], bh[0], bh[1]);
                    MMA16816(acc[1], ah[0], ah[1], ah[2], ah[3], bh[2], bh[3]);
                    MMA16816(acc[0], ah[0], ah[1], ah[2], ah[3], bl[0], bl[1]);
                    MMA16816(acc[1], ah[0], ah[1], ah[2], ah[3], bl[2], bl[3]);
                    MMA16816(acc[0], al[0], al[1], al[2], al[3], bh[0], bh[1]);
                    MMA16816(acc[1], al[0], al[1], al[2], al[3], bh[2], bh[3]);
                }
                // epilogue: bias, store k, Dopri5 combine, write yst (and y)
                float bm0 = b3g[16 * mt + qrow], bm1 = b3g[16 * mt + qrow + 8];
                float alast = c_A[st][st];
                #pragma unroll
                for (int f = 0; f < 2; ++f) {
                    #pragma unroll
                    for (int e = 0; e < 4; ++e) {
                        int dd = 16 * mt + qrow + ((e >> 1) << 3);
                        int s  = (2 * np + f) * 8 + 2 * qcol + (e & 1);
                        float v = acc[f][e] + ((e >> 1) ? bm1 : bm0);   // dy
                        int gidx = (gbase + s) * DB + dd;
                        if (st < 5) g_k[st][gidx] = v;
                        float comb = alast * v;
                        for (int m = 0; m < st; ++m)
                            comb += c_A[st][m] * g_k[m][gidx];
                        float nv = yt[s * LDF + dd] + dt * comb;
                        if (st == 5) yt[s * LDF + dd] = nv;
                        bsplit(nv, ysh[s * LDY + dd], ysl[s * LDY + dd]);
                    }
                }
            }
        } // stages
    } // steps

    __syncthreads();
    {
        const int d = tid & 63;
        const int srow = tid >> 6;
        #pragma unroll
        for (int c = 0; c < 8; ++c) {
            int s = srow * 8 + c;
            out[(gbase + s) * DB + d] = yt[s * LDF + d];
        }
        if (tid < SB) out[BT * DB + gbase + tid] = lds[tid];
    }
}

// ---------------------------------------------------------------------------
#define SMEM_BYTES ((4 * SB * LDH + 2 * SB * LDY) * 2 + (SB * LDF + 2 * SB) * 4)

extern "C" void kernel_launch(void* const* d_in, const int* in_sizes, int n_in,
                              void* d_out, int out_size) {
    const float* x   = (const float*)d_in[0];
    const float* ld0 = (const float*)d_in[1];
    const float* W1  = (const float*)d_in[2];
    const float* b1  = (const float*)d_in[3];
    const float* W2  = (const float*)d_in[4];
    const float* b2  = (const float*)d_in[5];
    const float* W3  = (const float*)d_in[6];
    const float* b3  = (const float*)d_in[7];
    const float* T   = (const float*)d_in[8];
    float* out = (float*)d_out;

    cudaFuncSetAttribute(cnf_main_kernel,
                         cudaFuncAttributeMaxDynamicSharedMemorySize, SMEM_BYTES);

    cnf_prep_kernel<<<HB, HB>>>(W1, W2, W3);
    cnf_main_kernel<<<NBLOCKS, NTHREADS, SMEM_BYTES>>>(x, ld0, b1, b2, b3, T, out);
}

// round 6
// speedup vs baseline: 6.6235x; 1.0788x over previous
#include <cuda_runtime.h>
#include <cuda_bf16.h>
#include <cstdint>

// ---------------------------------------------------------------------------
// CNF Dopri5 solver, tensor-core bf16 hi/lo 3-pass GEMMs.
// R6: 32 samples/CTA, 256 CTAs, 256 threads, 2 CTAs/SM for cross-CTA overlap.
// ---------------------------------------------------------------------------

#define DB 64
#define HB 256
#define BT 8192
#define NSTEPS 10
#define SB 32
#define NTHREADS 256
#define NBLOCKS (BT / SB)      // 256

#define LDH 264                // padded k-row for h arrays (bf16)
#define LDY 72                 // padded k-row for yst arrays
#define LDF 68                 // padded row for fp32 y

typedef __nv_bfloat16 bf16;

// Fragment-packed weights (A-operand order): uint4 index = (mtile*KC+kc)*32+lane.
__device__ __align__(16) bf16 g_W1hf[HB * DB], g_W1lf[HB * DB];     // M=256,K=64 (KC=4)
__device__ __align__(16) bf16 g_W2hf[HB * HB], g_W2lf[HB * HB];     // M=256,K=256 (KC=16)
__device__ __align__(16) bf16 g_Ehf [HB * HB], g_Elf [HB * HB];     // M=256,K=256
__device__ __align__(16) bf16 g_W3hf[DB * HB], g_W3lf[DB * HB];     // M=64, K=256
__device__ float g_k[5][BT * DB];                                   // k1..k5 fp32

__constant__ float c_A[6][6] = {
    { 0.2f, 0.f, 0.f, 0.f, 0.f, 0.f },
    { 3.f/40.f, 9.f/40.f, 0.f, 0.f, 0.f, 0.f },
    { 44.f/45.f, -56.f/15.f, 32.f/9.f, 0.f, 0.f, 0.f },
    { 19372.f/6561.f, -25360.f/2187.f, 64448.f/6561.f, -212.f/729.f, 0.f, 0.f },
    { 9017.f/3168.f, -355.f/33.f, 46732.f/5247.f, 49.f/176.f, -5103.f/18656.f, 0.f },
    { 35.f/384.f, 0.f, 500.f/1113.f, 125.f/192.f, -2187.f/6784.f, 11.f/84.f }
};
__constant__ float c_CL[6] = {
    35.f/384.f, 0.f, 500.f/1113.f, 125.f/192.f, -2187.f/6784.f, 11.f/84.f
};

__device__ __forceinline__ void bsplit(float v, bf16& hi, bf16& lo) {
    hi = __float2bfloat16(v);
    lo = __float2bfloat16(v - __bfloat162float(hi));
}

// Packed-fragment element index for A element (m,k) of a matrix with KC k-tiles.
__device__ __forceinline__ int pidx(int m, int k, int KC) {
    int mtile = m >> 4;
    int kc    = k >> 4;
    int lane  = (m & 7) * 4 + ((k & 7) >> 1);
    int reg   = ((k >> 3) & 1) * 2 + ((m >> 3) & 1);
    int half  = k & 1;
    return (((mtile * KC + kc) * 32 + lane) * 4 + reg) * 2 + half;
}

#define MMA16816(dd, a0, a1, a2, a3, bb0, bb1) \
    asm volatile("mma.sync.aligned.m16n8k16.row.col.f32.bf16.bf16.f32 " \
        "{%0,%1,%2,%3}, {%4,%5,%6,%7}, {%8,%9}, {%0,%1,%2,%3};" \
        : "+f"(dd[0]), "+f"(dd[1]), "+f"(dd[2]), "+f"(dd[3]) \
        : "r"(a0), "r"(a1), "r"(a2), "r"(a3), "r"(bb0), "r"(bb1))

// ldmatrix.x4: B-fragments for two adjacent n-tiles (nt0, nt0+1) at k-offset k0c.
__device__ __forceinline__ void ldsm_b(uint32_t r[4], const bf16* base,
                                       int nrow0, int ld, int k0c, int lane) {
    int mat = lane >> 3, rr = lane & 7;
    const bf16* p = base + (nrow0 + ((mat >> 1) << 3) + rr) * ld
                         + k0c + ((mat & 1) << 3);
    uint32_t saddr = (uint32_t)__cvta_generic_to_shared(p);
    asm volatile("ldmatrix.sync.aligned.m8n8.x4.shared.b16 {%0,%1,%2,%3}, [%4];"
        : "=r"(r[0]), "=r"(r[1]), "=r"(r[2]), "=r"(r[3]) : "r"(saddr));
}

__device__ __forceinline__ void ldfrag(const bf16* packed, int mtile, int KC,
                                       int kc, int lane, uint32_t a[4]) {
    uint4 v = ((const uint4*)packed)[(mtile * KC + kc) * 32 + lane];
    a[0] = v.x; a[1] = v.y; a[2] = v.z; a[3] = v.w;
}

// ---------------------------------------------------------------------------
// Prep: split weights hi/lo into packed fragment layout; E = W2 .* G^T.
// ---------------------------------------------------------------------------
__global__ void cnf_prep_kernel(const float* __restrict__ W1,
                                const float* __restrict__ W2,
                                const float* __restrict__ W3) {
    int i = blockIdx.x;
    int j = threadIdx.x;
    float g = 0.f;
    #pragma unroll
    for (int d = 0; d < DB; ++d)
        g += W1[i * DB + d] * W3[d * HB + j];
    {
        float ev = W2[j * HB + i] * g;
        int q = pidx(j, i, 16);
        bsplit(ev, g_Ehf[q], g_Elf[q]);
    }
    {
        int q = pidx(i, j, 16);
        bsplit(W2[i * HB + j], g_W2hf[q], g_W2lf[q]);
    }
    if (j < DB) {
        int q = pidx(i, j, 4);
        bsplit(W1[i * DB + j], g_W1hf[q], g_W1lf[q]);
    }
    if (i < DB) {
        int q = pidx(i, j, 16);
        bsplit(W3[i * HB + j], g_W3hf[q], g_W3lf[q]);
    }
}

// ---------------------------------------------------------------------------
// Main solver. grid=256, block=256, dyn smem ~86KB, 2 CTAs/SM.
// ---------------------------------------------------------------------------
__global__ void __launch_bounds__(NTHREADS, 2)
cnf_main_kernel(const float* __restrict__ x,
                const float* __restrict__ ld0,
                const float* __restrict__ b1g,
                const float* __restrict__ b2g,
                const float* __restrict__ b3g,
                const float* __restrict__ Tptr,
                float* __restrict__ out) {
    extern __shared__ char smraw[];
    bf16* h1h = (bf16*)smraw;            // [32][LDH]  h1 hi  (becomes h2 hi)
    bf16* h1l = h1h + SB * LDH;
    bf16* s1h = h1l + SB * LDH;
    bf16* s1l = s1h + SB * LDH;
    bf16* ysh = s1l + SB * LDH;          // [32][LDY]
    bf16* ysl = ysh + SB * LDY;
    float* yt = (float*)(ysl + SB * LDY);// [32][LDF]
    float* trs = yt + SB * LDF;
    float* lds = trs + SB;

    const int tid  = threadIdx.x;
    const int lane = tid & 31;
    const int w    = tid >> 5;           // warp 0..7
    const int qrow = lane >> 2;
    const int qcol = lane & 3;
    const int gbase = blockIdx.x * SB;

    const float dt = Tptr[0] * (1.0f / NSTEPS);

    {
        const int d = tid & 63;
        const int srow = tid >> 6;       // 0..3
        #pragma unroll
        for (int c = 0; c < 8; ++c) {
            int s = srow * 8 + c;
            float v = x[(gbase + s) * DB + d];
            yt[s * LDF + d] = v;
            bsplit(v, ysh[s * LDY + d], ysl[s * LDY + d]);
        }
        if (tid < SB) lds[tid] = ld0[gbase + tid];
    }

    for (int step = 0; step < NSTEPS; ++step) {
        for (int st = 0; st < 6; ++st) {
            __syncthreads();                    // yst ready
            if (tid < SB) trs[tid] = 0.f;

            // ================= Phase A: z1 = W1 yst + b1 =================
            {
                float acc[2][4][4];
                #pragma unroll
                for (int m2 = 0; m2 < 2; ++m2)
                    #pragma unroll
                    for (int nt = 0; nt < 4; ++nt)
                        #pragma unroll
                        for (int e = 0; e < 4; ++e) acc[m2][nt][e] = 0.f;

                #pragma unroll
                for (int kc = 0; kc < 4; ++kc) {
                    int k0c = kc * 16;
                    uint32_t bh[8], bl[8];
                    ldsm_b(&bh[0], ysh, 0,  LDY, k0c, lane);
                    ldsm_b(&bh[4], ysh, 16, LDY, k0c, lane);
                    ldsm_b(&bl[0], ysl, 0,  LDY, k0c, lane);
                    ldsm_b(&bl[4], ysl, 16, LDY, k0c, lane);
                    uint32_t ah[2][4], al[2][4];
                    #pragma unroll
                    for (int m2 = 0; m2 < 2; ++m2) {
                        ldfrag(g_W1hf, 2 * w + m2, 4, kc, lane, ah[m2]);
                        ldfrag(g_W1lf, 2 * w + m2, 4, kc, lane, al[m2]);
                    }
                    #pragma unroll
                    for (int m2 = 0; m2 < 2; ++m2)
                        #pragma unroll
                        for (int nt = 0; nt < 4; ++nt) {
                            uint32_t b0 = bh[(nt >> 1) * 4 + (nt & 1) * 2];
                            uint32_t b1 = bh[(nt >> 1) * 4 + (nt & 1) * 2 + 1];
                            MMA16816(acc[m2][nt], ah[m2][0], ah[m2][1], ah[m2][2], ah[m2][3], b0, b1);
                        }
                    #pragma unroll
                    for (int m2 = 0; m2 < 2; ++m2)
                        #pragma unroll
                        for (int nt = 0; nt < 4; ++nt) {
                            uint32_t b0 = bl[(nt >> 1) * 4 + (nt & 1) * 2];
                            uint32_t b1 = bl[(nt >> 1) * 4 + (nt & 1) * 2 + 1];
                            MMA16816(acc[m2][nt], ah[m2][0], ah[m2][1], ah[m2][2], ah[m2][3], b0, b1);
                        }
                    #pragma unroll
                    for (int m2 = 0; m2 < 2; ++m2)
                        #pragma unroll
                        for (int nt = 0; nt < 4; ++nt) {
                            uint32_t b0 = bh[(nt >> 1) * 4 + (nt & 1) * 2];
                            uint32_t b1 = bh[(nt >> 1) * 4 + (nt & 1) * 2 + 1];
                            MMA16816(acc[m2][nt], al[m2][0], al[m2][1], al[m2][2], al[m2][3], b0, b1);
                        }
                }
                // epilogue A
                #pragma unroll
                for (int m2 = 0; m2 < 2; ++m2) {
                    int mrow = 16 * (2 * w + m2);
                    float bm0 = b1g[mrow + qrow], bm1 = b1g[mrow + qrow + 8];
                    #pragma unroll
                    for (int nt = 0; nt < 4; ++nt) {
                        #pragma unroll
                        for (int e = 0; e < 4; ++e) {
                            int m = mrow + qrow + ((e >> 1) << 3);
                            int n = nt * 8 + 2 * qcol + (e & 1);
                            float z = acc[m2][nt][e] + ((e >> 1) ? bm1 : bm0);
                            float t = __expf(-fabsf(z));
                            float u = __fdividef(1.f, 1.f + t);
                            float sp = fmaxf(z, 0.f) + __logf(1.f + t);
                            float sg = (z > 0.f) ? u : 1.f - u;
                            bsplit(sp, h1h[n * LDH + m], h1l[n * LDH + m]);
                            bsplit(sg, s1h[n * LDH + m], s1l[n * LDH + m]);
                        }
                    }
                }
            }
            __syncthreads();                    // h1/s1 ready

            // ===== Phase B: z2 = W2 h1 + b2 ; t = E s1 ; trace; h2 =======
            float accZ[2][4][4], accT[2][4][4];
            {
                #pragma unroll
                for (int m2 = 0; m2 < 2; ++m2)
                    #pragma unroll
                    for (int nt = 0; nt < 4; ++nt)
                        #pragma unroll
                        for (int e = 0; e < 4; ++e) { accZ[m2][nt][e] = 0.f; accT[m2][nt][e] = 0.f; }

                // GEMM Z: W2 (hi/lo) x h1 (hi/lo)
                #pragma unroll 2
                for (int kc = 0; kc < 16; ++kc) {
                    int k0c = kc * 16;
                    uint32_t bh[8], bl[8];
                    ldsm_b(&bh[0], h1h, 0,  LDH, k0c, lane);
                    ldsm_b(&bh[4], h1h, 16, LDH, k0c, lane);
                    ldsm_b(&bl[0], h1l, 0,  LDH, k0c, lane);
                    ldsm_b(&bl[4], h1l, 16, LDH, k0c, lane);
                    uint32_t ah[2][4], al[2][4];
                    #pragma unroll
                    for (int m2 = 0; m2 < 2; ++m2) {
                        ldfrag(g_W2hf, 2 * w + m2, 16, kc, lane, ah[m2]);
                        ldfrag(g_W2lf, 2 * w + m2, 16, kc, lane, al[m2]);
                    }
                    #pragma unroll
                    for (int m2 = 0; m2 < 2; ++m2)
                        #pragma unroll
                        for (int nt = 0; nt < 4; ++nt) {
                            uint32_t b0 = bh[(nt >> 1) * 4 + (nt & 1) * 2];
                            uint32_t b1 = bh[(nt >> 1) * 4 + (nt & 1) * 2 + 1];
                            MMA16816(accZ[m2][nt], ah[m2][0], ah[m2][1], ah[m2][2], ah[m2][3], b0, b1);
                        }
                    #pragma unroll
                    for (int m2 = 0; m2 < 2; ++m2)
                        #pragma unroll
                        for (int nt = 0; nt < 4; ++nt) {
                            uint32_t b0 = bl[(nt >> 1) * 4 + (nt & 1) * 2];
                            uint32_t b1 = bl[(nt >> 1) * 4 + (nt & 1) * 2 + 1];
                            MMA16816(accZ[m2][nt], ah[m2][0], ah[m2][1], ah[m2][2], ah[m2][3], b0, b1);
                        }
                    #pragma unroll
                    for (int m2 = 0; m2 < 2; ++m2)
                        #pragma unroll
                        for (int nt = 0; nt < 4; ++nt) {
                            uint32_t b0 = bh[(nt >> 1) * 4 + (nt & 1) * 2];
                            uint32_t b1 = bh[(nt >> 1) * 4 + (nt & 1) * 2 + 1];
                            MMA16816(accZ[m2][nt], al[m2][0], al[m2][1], al[m2][2], al[m2][3], b0, b1);
                        }
                }
                // GEMM T: E (hi/lo) x s1 (hi/lo)
                #pragma unroll 2
                for (int kc = 0; kc < 16; ++kc) {
                    int k0c = kc * 16;
                    uint32_t bh[8], bl[8];
                    ldsm_b(&bh[0], s1h, 0,  LDH, k0c, lane);
                    ldsm_b(&bh[4], s1h, 16, LDH, k0c, lane);
                    ldsm_b(&bl[0], s1l, 0,  LDH, k0c, lane);
                    ldsm_b(&bl[4], s1l, 16, LDH, k0c, lane);
                    uint32_t ah[2][4], al[2][4];
                    #pragma unroll
                    for (int m2 = 0; m2 < 2; ++m2) {
                        ldfrag(g_Ehf, 2 * w + m2, 16, kc, lane, ah[m2]);
                        ldfrag(g_Elf, 2 * w + m2, 16, kc, lane, al[m2]);
                    }
                    #pragma unroll
                    for (int m2 = 0; m2 < 2; ++m2)
                        #pragma unroll
                        for (int nt = 0; nt < 4; ++nt) {
                            uint32_t b0 = bh[(nt >> 1) * 4 + (nt & 1) * 2];
                            uint32_t b1 = bh[(nt >> 1) * 4 + (nt & 1) * 2 + 1];
                            MMA16816(accT[m2][nt], ah[m2][0], ah[m2][1], ah[m2][2], ah[m2][3], b0, b1);
                        }
                    #pragma unroll
                    for (int m2 = 0; m2 < 2; ++m2)
                        #pragma unroll
                        for (int nt = 0; nt < 4; ++nt) {
                            uint32_t b0 = bl[(nt >> 1) * 4 + (nt & 1) * 2];
                            uint32_t b1 = bl[(nt >> 1) * 4 + (nt & 1) * 2 + 1];
                            MMA16816(accT[m2][nt], ah[m2][0], ah[m2][1], ah[m2][2], ah[m2][3], b0, b1);
                        }
                    #pragma unroll
                    for (int m2 = 0; m2 < 2; ++m2)
                        #pragma unroll
                        for (int nt = 0; nt < 4; ++nt) {
                            uint32_t b0 = bh[(nt >> 1) * 4 + (nt & 1) * 2];
                            uint32_t b1 = bh[(nt >> 1) * 4 + (nt & 1) * 2 + 1];
                            MMA16816(accT[m2][nt], al[m2][0], al[m2][1], al[m2][2], al[m2][3], b0, b1);
                        }
                }
            }
            __syncthreads();                    // all h1/s1 reads done

            // epilogue B: h2 = softplus(z2) into h1 arrays; trace partials
            {
                #pragma unroll
                for (int nt = 0; nt < 4; ++nt) {
                    float p0 = 0.f, p1 = 0.f;
                    #pragma unroll
                    for (int m2 = 0; m2 < 2; ++m2) {
                        int mrow = 16 * (2 * w + m2);
                        float bm0 = b2g[mrow + qrow], bm1 = b2g[mrow + qrow + 8];
                        #pragma unroll
                        for (int e = 0; e < 4; ++e) {
                            int m = mrow + qrow + ((e >> 1) << 3);
                            int n = nt * 8 + 2 * qcol + (e & 1);
                            float z = accZ[m2][nt][e] + ((e >> 1) ? bm1 : bm0);
                            float t = __expf(-fabsf(z));
                            float u = __fdividef(1.f, 1.f + t);
                            float sp = fmaxf(z, 0.f) + __logf(1.f + t);
                            float sg = (z > 0.f) ? u : 1.f - u;
                            bsplit(sp, h1h[n * LDH + m], h1l[n * LDH + m]);
                            float contrib = sg * accT[m2][nt][e];
                            if (e & 1) p1 += contrib; else p0 += contrib;
                        }
                    }
                    #pragma unroll
                    for (int msk = 4; msk <= 16; msk <<= 1) {
                        p0 += __shfl_xor_sync(0xFFFFFFFFu, p0, msk);
                        p1 += __shfl_xor_sync(0xFFFFFFFFu, p1, msk);
                    }
                    if (qrow == 0) {
                        atomicAdd(&trs[nt * 8 + 2 * qcol], p0);
                        atomicAdd(&trs[nt * 8 + 2 * qcol + 1], p1);
                    }
                }
            }
            __syncthreads();                    // h2 + trs ready

            if (tid < SB) lds[tid] += dt * c_CL[st] * trs[tid];

            // ===== Phase C: dy = W3 h2 + b3 ; k store; stage combine ======
            {
                const int mt = w & 3;           // m-tile over D=64
                const int np = w >> 2;          // 0..1, n-tile pair
                float acc[2][4];
                #pragma unroll
                for (int f = 0; f < 2; ++f)
                    #pragma unroll
                    for (int e = 0; e < 4; ++e) acc[f][e] = 0.f;

                #pragma unroll 4
                for (int kc = 0; kc < 16; ++kc) {
                    int k0c = kc * 16;
                    uint32_t bh[4], bl[4];
                    ldsm_b(bh, h1h, np * 16, LDH, k0c, lane);
                    ldsm_b(bl, h1l, np * 16, LDH, k0c, lane);
                    uint32_t ah[4], al[4];
                    ldfrag(g_W3hf, mt, 16, kc, lane, ah);
                    ldfrag(g_W3lf, mt, 16, kc, lane, al);
                    MMA16816(acc[0], ah[0], ah[1], ah[2], ah[3], bh[0], bh[1]);
                    MMA16816(acc[1], ah[0], ah[1], ah[2], ah[3], bh[2], bh[3]);
                    MMA16816(acc[0], ah[0], ah[1], ah[2], ah[3], bl[0], bl[1]);
                    MMA16816(acc[1], ah[0], ah[1], ah[2], ah[3], bl[2], bl[3]);
                    MMA16816(acc[0], al[0], al[1], al[2], al[3], bh[0], bh[1]);
                    MMA16816(acc[1], al[0], al[1], al[2], al[3], bh[2], bh[3]);
                }
                // epilogue: bias, store k, Dopri5 combine, write yst (and y)
                float bm0 = b3g[16 * mt + qrow], bm1 = b3g[16 * mt + qrow + 8];
                float alast = c_A[st][st];
                #pragma unroll
                for (int f = 0; f < 2; ++f) {
                    #pragma unroll
                    for (int e = 0; e < 4; ++e) {
                        int dd = 16 * mt + qrow + ((e >> 1) << 3);
                        int s  = (2 * np + f) * 8 + 2 * qcol + (e & 1);
                        float v = acc[f][e] + ((e >> 1) ? bm1 : bm0);   // dy
                        int gidx = (gbase + s) * DB + dd;
                        if (st < 5) g_k[st][gidx] = v;
                        float comb = alast * v;
                        for (int m = 0; m < st; ++m)
                            comb += c_A[st][m] * g_k[m][gidx];
                        float nv = yt[s * LDF + dd] + dt * comb;
                        if (st == 5) yt[s * LDF + dd] = nv;
                        bsplit(nv, ysh[s * LDY + dd], ysl[s * LDY + dd]);
                    }
                }
            }
        } // stages
    } // steps

    __syncthreads();
    {
        const int d = tid & 63;
        const int srow = tid >> 6;
        #pragma unroll
        for (int c = 0; c < 8; ++c) {
            int s = srow * 8 + c;
            out[(gbase + s) * DB + d] = yt[s * LDF + d];
        }
        if (tid < SB) out[BT * DB + gbase + tid] = lds[tid];
    }
}

// ---------------------------------------------------------------------------
#define SMEM_BYTES ((4 * SB * LDH + 2 * SB * LDY) * 2 + (SB * LDF + 2 * SB) * 4)

extern "C" void kernel_launch(void* const* d_in, const int* in_sizes, int n_in,
                              void* d_out, int out_size) {
    const float* x   = (const float*)d_in[0];
    const float* ld0 = (const float*)d_in[1];
    const float* W1  = (const float*)d_in[2];
    const float* b1  = (const float*)d_in[3];
    const float* W2  = (const float*)d_in[4];
    const float* b2  = (const float*)d_in[5];
    const float* W3  = (const float*)d_in[6];
    const float* b3  = (const float*)d_in[7];
    const float* T   = (const float*)d_in[8];
    float* out = (float*)d_out;

    cudaFuncSetAttribute(cnf_main_kernel,
                         cudaFuncAttributeMaxDynamicSharedMemorySize, SMEM_BYTES);

    cnf_prep_kernel<<<HB, HB>>>(W1, W2, W3);
    cnf_main_kernel<<<NBLOCKS, NTHREADS, SMEM_BYTES>>>(x, ld0, b1, b2, b3, T, out);
}

// round 7
// speedup vs baseline: 6.6589x; 1.0053x over previous
#include <cuda_runtime.h>
#include <cuda_bf16.h>
#include <cstdint>

// ---------------------------------------------------------------------------
// CNF Dopri5 solver, tensor-core bf16 hi/lo 3-pass GEMMs.
// R6: 32 samples/CTA, 256 CTAs, 256 threads, 2 CTAs/SM for cross-CTA overlap.
// ---------------------------------------------------------------------------

#define DB 64
#define HB 256
#define BT 8192
#define NSTEPS 10
#define SB 32
#define NTHREADS 256
#define NBLOCKS (BT / SB)      // 256

#define LDH 264                // padded k-row for h arrays (bf16)
#define LDY 72                 // padded k-row for yst arrays
#define LDF 68                 // padded row for fp32 y

typedef __nv_bfloat16 bf16;

// Fragment-packed weights (A-operand order): uint4 index = (mtile*KC+kc)*32+lane.
__device__ __align__(16) bf16 g_W1hf[HB * DB], g_W1lf[HB * DB];     // M=256,K=64 (KC=4)
__device__ __align__(16) bf16 g_W2hf[HB * HB], g_W2lf[HB * HB];     // M=256,K=256 (KC=16)
__device__ __align__(16) bf16 g_Ehf [HB * HB], g_Elf [HB * HB];     // M=256,K=256
__device__ __align__(16) bf16 g_W3hf[DB * HB], g_W3lf[DB * HB];     // M=64, K=256
__device__ float g_k[5][BT * DB];                                   // k1..k5 fp32

__constant__ float c_A[6][6] = {
    { 0.2f, 0.f, 0.f, 0.f, 0.f, 0.f },
    { 3.f/40.f, 9.f/40.f, 0.f, 0.f, 0.f, 0.f },
    { 44.f/45.f, -56.f/15.f, 32.f/9.f, 0.f, 0.f, 0.f },
    { 19372.f/6561.f, -25360.f/2187.f, 64448.f/6561.f, -212.f/729.f, 0.f, 0.f },
    { 9017.f/3168.f, -355.f/33.f, 46732.f/5247.f, 49.f/176.f, -5103.f/18656.f, 0.f },
    { 35.f/384.f, 0.f, 500.f/1113.f, 125.f/192.f, -2187.f/6784.f, 11.f/84.f }
};
__constant__ float c_CL[6] = {
    35.f/384.f, 0.f, 500.f/1113.f, 125.f/192.f, -2187.f/6784.f, 11.f/84.f
};

__device__ __forceinline__ void bsplit(float v, bf16& hi, bf16& lo) {
    hi = __float2bfloat16(v);
    lo = __float2bfloat16(v - __bfloat162float(hi));
}

// Packed-fragment element index for A element (m,k) of a matrix with KC k-tiles.
__device__ __forceinline__ int pidx(int m, int k, int KC) {
    int mtile = m >> 4;
    int kc    = k >> 4;
    int lane  = (m & 7) * 4 + ((k & 7) >> 1);
    int reg   = ((k >> 3) & 1) * 2 + ((m >> 3) & 1);
    int half  = k & 1;
    return (((mtile * KC + kc) * 32 + lane) * 4 + reg) * 2 + half;
}

#define MMA16816(dd, a0, a1, a2, a3, bb0, bb1) \
    asm volatile("mma.sync.aligned.m16n8k16.row.col.f32.bf16.bf16.f32 " \
        "{%0,%1,%2,%3}, {%4,%5,%6,%7}, {%8,%9}, {%0,%1,%2,%3};" \
        : "+f"(dd[0]), "+f"(dd[1]), "+f"(dd[2]), "+f"(dd[3]) \
        : "r"(a0), "r"(a1), "r"(a2), "r"(a3), "r"(bb0), "r"(bb1))

// ldmatrix.x4: B-fragments for two adjacent n-tiles (nt0, nt0+1) at k-offset k0c.
__device__ __forceinline__ void ldsm_b(uint32_t r[4], const bf16* base,
                                       int nrow0, int ld, int k0c, int lane) {
    int mat = lane >> 3, rr = lane & 7;
    const bf16* p = base + (nrow0 + ((mat >> 1) << 3) + rr) * ld
                         + k0c + ((mat & 1) << 3);
    uint32_t saddr = (uint32_t)__cvta_generic_to_shared(p);
    asm volatile("ldmatrix.sync.aligned.m8n8.x4.shared.b16 {%0,%1,%2,%3}, [%4];"
        : "=r"(r[0]), "=r"(r[1]), "=r"(r[2]), "=r"(r[3]) : "r"(saddr));
}

__device__ __forceinline__ void ldfrag(const bf16* packed, int mtile, int KC,
                                       int kc, int lane, uint32_t a[4]) {
    uint4 v = ((const uint4*)packed)[(mtile * KC + kc) * 32 + lane];
    a[0] = v.x; a[1] = v.y; a[2] = v.z; a[3] = v.w;
}

// ---------------------------------------------------------------------------
// Prep: split weights hi/lo into packed fragment layout; E = W2 .* G^T.
// ---------------------------------------------------------------------------
__global__ void cnf_prep_kernel(const float* __restrict__ W1,
                                const float* __restrict__ W2,
                                const float* __restrict__ W3) {
    int i = blockIdx.x;
    int j = threadIdx.x;
    float g = 0.f;
    #pragma unroll
    for (int d = 0; d < DB; ++d)
        g += W1[i * DB + d] * W3[d * HB + j];
    {
        float ev = W2[j * HB + i] * g;
        int q = pidx(j, i, 16);
        bsplit(ev, g_Ehf[q], g_Elf[q]);
    }
    {
        int q = pidx(i, j, 16);
        bsplit(W2[i * HB + j], g_W2hf[q], g_W2lf[q]);
    }
    if (j < DB) {
        int q = pidx(i, j, 4);
        bsplit(W1[i * DB + j], g_W1hf[q], g_W1lf[q]);
    }
    if (i < DB) {
        int q = pidx(i, j, 16);
        bsplit(W3[i * HB + j], g_W3hf[q], g_W3lf[q]);
    }
}

// ---------------------------------------------------------------------------
// Main solver. grid=256, block=256, dyn smem ~86KB, 2 CTAs/SM.
// ---------------------------------------------------------------------------
__global__ void __launch_bounds__(NTHREADS, 2)
cnf_main_kernel(const float* __restrict__ x,
                const float* __restrict__ ld0,
                const float* __restrict__ b1g,
                const float* __restrict__ b2g,
                const float* __restrict__ b3g,
                const float* __restrict__ Tptr,
                float* __restrict__ out) {
    extern __shared__ char smraw[];
    bf16* h1h = (bf16*)smraw;            // [32][LDH]  h1 hi  (becomes h2 hi)
    bf16* h1l = h1h + SB * LDH;
    bf16* s1h = h1l + SB * LDH;
    bf16* s1l = s1h + SB * LDH;
    bf16* ysh = s1l + SB * LDH;          // [32][LDY]
    bf16* ysl = ysh + SB * LDY;
    float* yt = (float*)(ysl + SB * LDY);// [32][LDF]
    float* trs = yt + SB * LDF;
    float* lds = trs + SB;

    const int tid  = threadIdx.x;
    const int lane = tid & 31;
    const int w    = tid >> 5;           // warp 0..7
    const int qrow = lane >> 2;
    const int qcol = lane & 3;
    const int gbase = blockIdx.x * SB;

    const float dt = Tptr[0] * (1.0f / NSTEPS);

    {
        const int d = tid & 63;
        const int srow = tid >> 6;       // 0..3
        #pragma unroll
        for (int c = 0; c < 8; ++c) {
            int s = srow * 8 + c;
            float v = x[(gbase + s) * DB + d];
            yt[s * LDF + d] = v;
            bsplit(v, ysh[s * LDY + d], ysl[s * LDY + d]);
        }
        if (tid < SB) lds[tid] = ld0[gbase + tid];
    }

    for (int step = 0; step < NSTEPS; ++step) {
        for (int st = 0; st < 6; ++st) {
            __syncthreads();                    // yst ready
            if (tid < SB) trs[tid] = 0.f;

            // ================= Phase A: z1 = W1 yst + b1 =================
            {
                float acc[2][4][4];
                #pragma unroll
                for (int m2 = 0; m2 < 2; ++m2)
                    #pragma unroll
                    for (int nt = 0; nt < 4; ++nt)
                        #pragma unroll
                        for (int e = 0; e < 4; ++e) acc[m2][nt][e] = 0.f;

                #pragma unroll
                for (int kc = 0; kc < 4; ++kc) {
                    int k0c = kc * 16;
                    uint32_t bh[8], bl[8];
                    ldsm_b(&bh[0], ysh, 0,  LDY, k0c, lane);
                    ldsm_b(&bh[4], ysh, 16, LDY, k0c, lane);
                    ldsm_b(&bl[0], ysl, 0,  LDY, k0c, lane);
                    ldsm_b(&bl[4], ysl, 16, LDY, k0c, lane);
                    uint32_t ah[2][4], al[2][4];
                    #pragma unroll
                    for (int m2 = 0; m2 < 2; ++m2) {
                        ldfrag(g_W1hf, 2 * w + m2, 4, kc, lane, ah[m2]);
                        ldfrag(g_W1lf, 2 * w + m2, 4, kc, lane, al[m2]);
                    }
                    #pragma unroll
                    for (int m2 = 0; m2 < 2; ++m2)
                        #pragma unroll
                        for (int nt = 0; nt < 4; ++nt) {
                            uint32_t b0 = bh[(nt >> 1) * 4 + (nt & 1) * 2];
                            uint32_t b1 = bh[(nt >> 1) * 4 + (nt & 1) * 2 + 1];
                            MMA16816(acc[m2][nt], ah[m2][0], ah[m2][1], ah[m2][2], ah[m2][3], b0, b1);
                        }
                    #pragma unroll
                    for (int m2 = 0; m2 < 2; ++m2)
                        #pragma unroll
                        for (int nt = 0; nt < 4; ++nt) {
                            uint32_t b0 = bl[(nt >> 1) * 4 + (nt & 1) * 2];
                            uint32_t b1 = bl[(nt >> 1) * 4 + (nt & 1) * 2 + 1];
                            MMA16816(acc[m2][nt], ah[m2][0], ah[m2][1], ah[m2][2], ah[m2][3], b0, b1);
                        }
                    #pragma unroll
                    for (int m2 = 0; m2 < 2; ++m2)
                        #pragma unroll
                        for (int nt = 0; nt < 4; ++nt) {
                            uint32_t b0 = bh[(nt >> 1) * 4 + (nt & 1) * 2];
                            uint32_t b1 = bh[(nt >> 1) * 4 + (nt & 1) * 2 + 1];
                            MMA16816(acc[m2][nt], al[m2][0], al[m2][1], al[m2][2], al[m2][3], b0, b1);
                        }
                }
                // epilogue A
                #pragma unroll
                for (int m2 = 0; m2 < 2; ++m2) {
                    int mrow = 16 * (2 * w + m2);
                    float bm0 = b1g[mrow + qrow], bm1 = b1g[mrow + qrow + 8];
                    #pragma unroll
                    for (int nt = 0; nt < 4; ++nt) {
                        #pragma unroll
                        for (int e = 0; e < 4; ++e) {
                            int m = mrow + qrow + ((e >> 1) << 3);
                            int n = nt * 8 + 2 * qcol + (e & 1);
                            float z = acc[m2][nt][e] + ((e >> 1) ? bm1 : bm0);
                            float t = __expf(-fabsf(z));
                            float u = __fdividef(1.f, 1.f + t);
                            float sp = fmaxf(z, 0.f) + __logf(1.f + t);
                            float sg = (z > 0.f) ? u : 1.f - u;
                            bsplit(sp, h1h[n * LDH + m], h1l[n * LDH + m]);
                            bsplit(sg, s1h[n * LDH + m], s1l[n * LDH + m]);
                        }
                    }
                }
            }
            __syncthreads();                    // h1/s1 ready

            // ===== Phase B: z2 = W2 h1 + b2 ; t = E s1 ; trace; h2 =======
            float accZ[2][4][4], accT[2][4][4];
            {
                #pragma unroll
                for (int m2 = 0; m2 < 2; ++m2)
                    #pragma unroll
                    for (int nt = 0; nt < 4; ++nt)
                        #pragma unroll
                        for (int e = 0; e < 4; ++e) { accZ[m2][nt][e] = 0.f; accT[m2][nt][e] = 0.f; }

                // GEMM Z: W2 (hi/lo) x h1 (hi/lo)
                #pragma unroll 2
                for (int kc = 0; kc < 16; ++kc) {
                    int k0c = kc * 16;
                    uint32_t bh[8], bl[8];
                    ldsm_b(&bh[0], h1h, 0,  LDH, k0c, lane);
                    ldsm_b(&bh[4], h1h, 16, LDH, k0c, lane);
                    ldsm_b(&bl[0], h1l, 0,  LDH, k0c, lane);
                    ldsm_b(&bl[4], h1l, 16, LDH, k0c, lane);
                    uint32_t ah[2][4], al[2][4];
                    #pragma unroll
                    for (int m2 = 0; m2 < 2; ++m2) {
                        ldfrag(g_W2hf, 2 * w + m2, 16, kc, lane, ah[m2]);
                        ldfrag(g_W2lf, 2 * w + m2, 16, kc, lane, al[m2]);
                    }
                    #pragma unroll
                    for (int m2 = 0; m2 < 2; ++m2)
                        #pragma unroll
                        for (int nt = 0; nt < 4; ++nt) {
                            uint32_t b0 = bh[(nt >> 1) * 4 + (nt & 1) * 2];
                            uint32_t b1 = bh[(nt >> 1) * 4 + (nt & 1) * 2 + 1];
                            MMA16816(accZ[m2][nt], ah[m2][0], ah[m2][1], ah[m2][2], ah[m2][3], b0, b1);
                        }
                    #pragma unroll
                    for (int m2 = 0; m2 < 2; ++m2)
                        #pragma unroll
                        for (int nt = 0; nt < 4; ++nt) {
                            uint32_t b0 = bl[(nt >> 1) * 4 + (nt & 1) * 2];
                            uint32_t b1 = bl[(nt >> 1) * 4 + (nt & 1) * 2 + 1];
                            MMA16816(accZ[m2][nt], ah[m2][0], ah[m2][1], ah[m2][2], ah[m2][3], b0, b1);
                        }
                    #pragma unroll
                    for (int m2 = 0; m2 < 2; ++m2)
                        #pragma unroll
                        for (int nt = 0; nt < 4; ++nt) {
                            uint32_t b0 = bh[(nt >> 1) * 4 + (nt & 1) * 2];
                            uint32_t b1 = bh[(nt >> 1) * 4 + (nt & 1) * 2 + 1];
                            MMA16816(accZ[m2][nt], al[m2][0], al[m2][1], al[m2][2], al[m2][3], b0, b1);
                        }
                }
                // GEMM T: E (hi/lo) x s1 (hi/lo)
                #pragma unroll 2
                for (int kc = 0; kc < 16; ++kc) {
                    int k0c = kc * 16;
                    uint32_t bh[8], bl[8];
                    ldsm_b(&bh[0], s1h, 0,  LDH, k0c, lane);
                    ldsm_b(&bh[4], s1h, 16, LDH, k0c, lane);
                    ldsm_b(&bl[0], s1l, 0,  LDH, k0c, lane);
                    ldsm_b(&bl[4], s1l, 16, LDH, k0c, lane);
                    uint32_t ah[2][4], al[2][4];
                    #pragma unroll
                    for (int m2 = 0; m2 < 2; ++m2) {
                        ldfrag(g_Ehf, 2 * w + m2, 16, kc, lane, ah[m2]);
                        ldfrag(g_Elf, 2 * w + m2, 16, kc, lane, al[m2]);
                    }
                    #pragma unroll
                    for (int m2 = 0; m2 < 2; ++m2)
                        #pragma unroll
                        for (int nt = 0; nt < 4; ++nt) {
                            uint32_t b0 = bh[(nt >> 1) * 4 + (nt & 1) * 2];
                            uint32_t b1 = bh[(nt >> 1) * 4 + (nt & 1) * 2 + 1];
                            MMA16816(accT[m2][nt], ah[m2][0], ah[m2][1], ah[m2][2], ah[m2][3], b0, b1);
                        }
                    #pragma unroll
                    for (int m2 = 0; m2 < 2; ++m2)
                        #pragma unroll
                        for (int nt = 0; nt < 4; ++nt) {
                            uint32_t b0 = bl[(nt >> 1) * 4 + (nt & 1) * 2];
                            uint32_t b1 = bl[(nt >> 1) * 4 + (nt & 1) * 2 + 1];
                            MMA16816(accT[m2][nt], ah[m2][0], ah[m2][1], ah[m2][2], ah[m2][3], b0, b1);
                        }
                    #pragma unroll
                    for (int m2 = 0; m2 < 2; ++m2)
                        #pragma unroll
                        for (int nt = 0; nt < 4; ++nt) {
                            uint32_t b0 = bh[(nt >> 1) * 4 + (nt & 1) * 2];
                            uint32_t b1 = bh[(nt >> 1) * 4 + (nt & 1) * 2 + 1];
                            MMA16816(accT[m2][nt], al[m2][0], al[m2][1], al[m2][2], al[m2][3], b0, b1);
                        }
                }
            }
            __syncthreads();                    // all h1/s1 reads done

            // epilogue B: h2 = softplus(z2) into h1 arrays; trace partials
            {
                #pragma unroll
                for (int nt = 0; nt < 4; ++nt) {
                    float p0 = 0.f, p1 = 0.f;
                    #pragma unroll
                    for (int m2 = 0; m2 < 2; ++m2) {
                        int mrow = 16 * (2 * w + m2);
                        float bm0 = b2g[mrow + qrow], bm1 = b2g[mrow + qrow + 8];
                        #pragma unroll
                        for (int e = 0; e < 4; ++e) {
                            int m = mrow + qrow + ((e >> 1) << 3);
                            int n = nt * 8 + 2 * qcol + (e & 1);
                            float z = accZ[m2][nt][e] + ((e >> 1) ? bm1 : bm0);
                            float t = __expf(-fabsf(z));
                            float u = __fdividef(1.f, 1.f + t);
                            float sp = fmaxf(z, 0.f) + __logf(1.f + t);
                            float sg = (z > 0.f) ? u : 1.f - u;
                            bsplit(sp, h1h[n * LDH + m], h1l[n * LDH + m]);
                            float contrib = sg * accT[m2][nt][e];
                            if (e & 1) p1 += contrib; else p0 += contrib;
                        }
                    }
                    #pragma unroll
                    for (int msk = 4; msk <= 16; msk <<= 1) {
                        p0 += __shfl_xor_sync(0xFFFFFFFFu, p0, msk);
                        p1 += __shfl_xor_sync(0xFFFFFFFFu, p1, msk);
                    }
                    if (qrow == 0) {
                        atomicAdd(&trs[nt * 8 + 2 * qcol], p0);
                        atomicAdd(&trs[nt * 8 + 2 * qcol + 1], p1);
                    }
                }
            }
            __syncthreads();                    // h2 + trs ready

            if (tid < SB) lds[tid] += dt * c_CL[st] * trs[tid];

            // ===== Phase C: dy = W3 h2 + b3 ; k store; stage combine ======
            {
                const int mt = w & 3;           // m-tile over D=64
                const int np = w >> 2;          // 0..1, n-tile pair
                float acc[2][4];
                #pragma unroll
                for (int f = 0; f < 2; ++f)
                    #pragma unroll
                    for (int e = 0; e < 4; ++e) acc[f][e] = 0.f;

                #pragma unroll 4
                for (int kc = 0; kc < 16; ++kc) {
                    int k0c = kc * 16;
                    uint32_t bh[4], bl[4];
                    ldsm_b(bh, h1h, np * 16, LDH, k0c, lane);
                    ldsm_b(bl, h1l, np * 16, LDH, k0c, lane);
                    uint32_t ah[4], al[4];
                    ldfrag(g_W3hf, mt, 16, kc, lane, ah);
                    ldfrag(g_W3lf, mt, 16, kc, lane, al);
                    MMA16816(acc[0], ah[0], ah[1], ah[2], ah[3], bh[0], bh[1]);
                    MMA16816(acc[1], ah[0], ah[1], ah[2], ah[3], bh[2], bh[3]);
                    MMA16816(acc[0], ah[0], ah[1], ah[2], ah[3], bl[0], bl[1]);
                    MMA16816(acc[1], ah[0], ah[1], ah[2], ah[3], bl[2], bl[3]);
                    MMA16816(acc[0], al[0], al[1], al[2], al[3], bh[0], bh[1]);
                    MMA16816(acc[1], al[0], al[1], al[2], al[3], bh[2], bh[3]);
                }
                // epilogue: bias, store k, Dopri5 combine, write yst (and y)
                float bm0 = b3g[16 * mt + qrow], bm1 = b3g[16 * mt + qrow + 8];
                float alast = c_A[st][st];
                #pragma unroll
                for (int f = 0; f < 2; ++f) {
                    #pragma unroll
                    for (int e = 0; e < 4; ++e) {
                        int dd = 16 * mt + qrow + ((e >> 1) << 3);
                        int s  = (2 * np + f) * 8 + 2 * qcol + (e & 1);
                        float v = acc[f][e] + ((e >> 1) ? bm1 : bm0);   // dy
                        int gidx = (gbase + s) * DB + dd;
                        if (st < 5) g_k[st][gidx] = v;
                        float comb = alast * v;
                        for (int m = 0; m < st; ++m)
                            comb += c_A[st][m] * g_k[m][gidx];
                        float nv = yt[s * LDF + dd] + dt * comb;
                        if (st == 5) yt[s * LDF + dd] = nv;
                        bsplit(nv, ysh[s * LDY + dd], ysl[s * LDY + dd]);
                    }
                }
            }
        } // stages
    } // steps

    __syncthreads();
    {
        const int d = tid & 63;
        const int srow = tid >> 6;
        #pragma unroll
        for (int c = 0; c < 8; ++c) {
            int s = srow * 8 + c;
            out[(gbase + s) * DB + d] = yt[s * LDF + d];
        }
        if (tid < SB) out[BT * DB + gbase + tid] = lds[tid];
    }
}

// ---------------------------------------------------------------------------
#define SMEM_BYTES ((4 * SB * LDH + 2 * SB * LDY) * 2 + (SB * LDF + 2 * SB) * 4)

extern "C" void kernel_launch(void* const* d_in, const int* in_sizes, int n_in,
                              void* d_out, int out_size) {
    const float* x   = (const float*)d_in[0];
    const float* ld0 = (const float*)d_in[1];
    const float* W1  = (const float*)d_in[2];
    const float* b1  = (const float*)d_in[3];
    const float* W2  = (const float*)d_in[4];
    const float* b2  = (const float*)d_in[5];
    const float* W3  = (const float*)d_in[6];
    const float* b3  = (const float*)d_in[7];
    const float* T   = (const float*)d_in[8];
    float* out = (float*)d_out;

    cudaFuncSetAttribute(cnf_main_kernel,
                         cudaFuncAttributeMaxDynamicSharedMemorySize, SMEM_BYTES);

    cnf_prep_kernel<<<HB, HB>>>(W1, W2, W3);
    cnf_main_kernel<<<NBLOCKS, NTHREADS, SMEM_BYTES>>>(x, ld0, b1, b2, b3, T, out);
}

// round 8
// speedup vs baseline: 8.8482x; 1.3288x over previous
#include <cuda_runtime.h>
#include <cuda_fp16.h>
#include <cstdint>

// ---------------------------------------------------------------------------
// CNF Dopri5 solver, tensor-core GEMMs.
// R8: fp16 2-pass (weights hi/lo fp16, activations single fp16).
// 32 samples/CTA, 256 CTAs, 256 threads, 2 CTAs/SM.
// ---------------------------------------------------------------------------

#define DB 64
#define HB 256
#define BT 8192
#define NSTEPS 10
#define SB 32
#define NTHREADS 256
#define NBLOCKS (BT / SB)      // 256

#define LDH 264                // padded k-row for h/s arrays (fp16)
#define LDY 72                 // padded k-row for yst array
#define LDF 68                 // padded row for fp32 y

typedef __half f16;

// Fragment-packed weights hi/lo fp16: uint4 index = (mtile*KC+kc)*32+lane.
__device__ __align__(16) f16 g_W1hf[HB * DB], g_W1lf[HB * DB];     // M=256,K=64 (KC=4)
__device__ __align__(16) f16 g_W2hf[HB * HB], g_W2lf[HB * HB];     // M=256,K=256 (KC=16)
__device__ __align__(16) f16 g_Ehf [HB * HB], g_Elf [HB * HB];     // M=256,K=256
__device__ __align__(16) f16 g_W3hf[DB * HB], g_W3lf[DB * HB];     // M=64, K=256
__device__ float g_k[5][BT * DB];                                  // k1..k5 fp32

__constant__ float c_A[6][6] = {
    { 0.2f, 0.f, 0.f, 0.f, 0.f, 0.f },
    { 3.f/40.f, 9.f/40.f, 0.f, 0.f, 0.f, 0.f },
    { 44.f/45.f, -56.f/15.f, 32.f/9.f, 0.f, 0.f, 0.f },
    { 19372.f/6561.f, -25360.f/2187.f, 64448.f/6561.f, -212.f/729.f, 0.f, 0.f },
    { 9017.f/3168.f, -355.f/33.f, 46732.f/5247.f, 49.f/176.f, -5103.f/18656.f, 0.f },
    { 35.f/384.f, 0.f, 500.f/1113.f, 125.f/192.f, -2187.f/6784.f, 11.f/84.f }
};
__constant__ float c_CL[6] = {
    35.f/384.f, 0.f, 500.f/1113.f, 125.f/192.f, -2187.f/6784.f, 11.f/84.f
};

__device__ __forceinline__ void wsplit(float v, f16& hi, f16& lo) {
    hi = __float2half(v);
    lo = __float2half(v - __half2float(hi));
}

// Packed-fragment element index for A element (m,k) of a matrix with KC k-tiles.
__device__ __forceinline__ int pidx(int m, int k, int KC) {
    int mtile = m >> 4;
    int kc    = k >> 4;
    int lane  = (m & 7) * 4 + ((k & 7) >> 1);
    int reg   = ((k >> 3) & 1) * 2 + ((m >> 3) & 1);
    int half_ = k & 1;
    return (((mtile * KC + kc) * 32 + lane) * 4 + reg) * 2 + half_;
}

#define MMA16816(dd, a0, a1, a2, a3, bb0, bb1) \
    asm volatile("mma.sync.aligned.m16n8k16.row.col.f32.f16.f16.f32 " \
        "{%0,%1,%2,%3}, {%4,%5,%6,%7}, {%8,%9}, {%0,%1,%2,%3};" \
        : "+f"(dd[0]), "+f"(dd[1]), "+f"(dd[2]), "+f"(dd[3]) \
        : "r"(a0), "r"(a1), "r"(a2), "r"(a3), "r"(bb0), "r"(bb1))

// ldmatrix.x4: B-fragments for two adjacent n-tiles at k-offset k0c.
__device__ __forceinline__ void ldsm_b(uint32_t r[4], const f16* base,
                                       int nrow0, int ld, int k0c, int lane) {
    int mat = lane >> 3, rr = lane & 7;
    const f16* p = base + (nrow0 + ((mat >> 1) << 3) + rr) * ld
                        + k0c + ((mat & 1) << 3);
    uint32_t saddr = (uint32_t)__cvta_generic_to_shared(p);
    asm volatile("ldmatrix.sync.aligned.m8n8.x4.shared.b16 {%0,%1,%2,%3}, [%4];"
        : "=r"(r[0]), "=r"(r[1]), "=r"(r[2]), "=r"(r[3]) : "r"(saddr));
}

__device__ __forceinline__ void ldfrag(const f16* packed, int mtile, int KC,
                                       int kc, int lane, uint32_t a[4]) {
    uint4 v = ((const uint4*)packed)[(mtile * KC + kc) * 32 + lane];
    a[0] = v.x; a[1] = v.y; a[2] = v.z; a[3] = v.w;
}

// ---------------------------------------------------------------------------
// Prep: split weights hi/lo fp16 into packed fragment layout; E = W2 .* G^T.
// ---------------------------------------------------------------------------
__global__ void cnf_prep_kernel(const float* __restrict__ W1,
                                const float* __restrict__ W2,
                                const float* __restrict__ W3) {
    int i = blockIdx.x;
    int j = threadIdx.x;
    float g = 0.f;
    #pragma unroll
    for (int d = 0; d < DB; ++d)
        g += W1[i * DB + d] * W3[d * HB + j];
    {
        float ev = W2[j * HB + i] * g;     // E[j][i]
        int q = pidx(j, i, 16);
        wsplit(ev, g_Ehf[q], g_Elf[q]);
    }
    {
        int q = pidx(i, j, 16);
        wsplit(W2[i * HB + j], g_W2hf[q], g_W2lf[q]);
    }
    if (j < DB) {
        int q = pidx(i, j, 4);
        wsplit(W1[i * DB + j], g_W1hf[q], g_W1lf[q]);
    }
    if (i < DB) {
        int q = pidx(i, j, 16);
        wsplit(W3[i * HB + j], g_W3hf[q], g_W3lf[q]);
    }
}

// ---------------------------------------------------------------------------
// Main solver. grid=256, block=256, dyn smem ~47KB, 2 CTAs/SM.
// ---------------------------------------------------------------------------
__global__ void __launch_bounds__(NTHREADS, 2)
cnf_main_kernel(const float* __restrict__ x,
                const float* __restrict__ ld0,
                const float* __restrict__ b1g,
                const float* __restrict__ b2g,
                const float* __restrict__ b3g,
                const float* __restrict__ Tptr,
                float* __restrict__ out) {
    extern __shared__ char smraw[];
    f16* h1s = (f16*)smraw;              // [32][LDH]  h1 (becomes h2)
    f16* s1s = h1s + SB * LDH;           // [32][LDH]  sigmoid
    f16* ys  = s1s + SB * LDH;           // [32][LDY]  stage argument
    float* yt = (float*)(ys + SB * LDY); // [32][LDF]  master y fp32
    float* trs = yt + SB * LDF;
    float* lds = trs + SB;

    const int tid  = threadIdx.x;
    const int lane = tid & 31;
    const int w    = tid >> 5;           // warp 0..7
    const int qrow = lane >> 2;
    const int qcol = lane & 3;
    const int gbase = blockIdx.x * SB;

    const float dt = Tptr[0] * (1.0f / NSTEPS);

    {
        const int d = tid & 63;
        const int srow = tid >> 6;       // 0..3
        #pragma unroll
        for (int c = 0; c < 8; ++c) {
            int s = srow * 8 + c;
            float v = x[(gbase + s) * DB + d];
            yt[s * LDF + d] = v;
            ys[s * LDY + d] = __float2half(v);
        }
        if (tid < SB) lds[tid] = ld0[gbase + tid];
    }

    for (int step = 0; step < NSTEPS; ++step) {
        for (int st = 0; st < 6; ++st) {
            __syncthreads();                    // yst ready
            if (tid < SB) trs[tid] = 0.f;

            // ================= Phase A: z1 = W1 yst + b1 =================
            {
                float acc[2][4][4];
                #pragma unroll
                for (int m2 = 0; m2 < 2; ++m2)
                    #pragma unroll
                    for (int nt = 0; nt < 4; ++nt)
                        #pragma unroll
                        for (int e = 0; e < 4; ++e) acc[m2][nt][e] = 0.f;

                #pragma unroll
                for (int kc = 0; kc < 4; ++kc) {
                    int k0c = kc * 16;
                    uint32_t bh[8];
                    ldsm_b(&bh[0], ys, 0,  LDY, k0c, lane);
                    ldsm_b(&bh[4], ys, 16, LDY, k0c, lane);
                    uint32_t ah[2][4], al[2][4];
                    #pragma unroll
                    for (int m2 = 0; m2 < 2; ++m2) {
                        ldfrag(g_W1hf, 2 * w + m2, 4, kc, lane, ah[m2]);
                        ldfrag(g_W1lf, 2 * w + m2, 4, kc, lane, al[m2]);
                    }
                    #pragma unroll
                    for (int m2 = 0; m2 < 2; ++m2)
                        #pragma unroll
                        for (int nt = 0; nt < 4; ++nt) {
                            uint32_t b0 = bh[(nt >> 1) * 4 + (nt & 1) * 2];
                            uint32_t b1 = bh[(nt >> 1) * 4 + (nt & 1) * 2 + 1];
                            MMA16816(acc[m2][nt], ah[m2][0], ah[m2][1], ah[m2][2], ah[m2][3], b0, b1);
                        }
                    #pragma unroll
                    for (int m2 = 0; m2 < 2; ++m2)
                        #pragma unroll
                        for (int nt = 0; nt < 4; ++nt) {
                            uint32_t b0 = bh[(nt >> 1) * 4 + (nt & 1) * 2];
                            uint32_t b1 = bh[(nt >> 1) * 4 + (nt & 1) * 2 + 1];
                            MMA16816(acc[m2][nt], al[m2][0], al[m2][1], al[m2][2], al[m2][3], b0, b1);
                        }
                }
                // epilogue A
                #pragma unroll
                for (int m2 = 0; m2 < 2; ++m2) {
                    int mrow = 16 * (2 * w + m2);
                    float bm0 = b1g[mrow + qrow], bm1 = b1g[mrow + qrow + 8];
                    #pragma unroll
                    for (int nt = 0; nt < 4; ++nt) {
                        #pragma unroll
                        for (int e = 0; e < 4; ++e) {
                            int m = mrow + qrow + ((e >> 1) << 3);
                            int n = nt * 8 + 2 * qcol + (e & 1);
                            float z = acc[m2][nt][e] + ((e >> 1) ? bm1 : bm0);
                            float t = __expf(-fabsf(z));
                            float u = __fdividef(1.f, 1.f + t);
                            float sp = fmaxf(z, 0.f) + __logf(1.f + t);
                            float sg = (z > 0.f) ? u : 1.f - u;
                            h1s[n * LDH + m] = __float2half(sp);
                            s1s[n * LDH + m] = __float2half(sg);
                        }
                    }
                }
            }
            __syncthreads();                    // h1/s1 ready

            // ===== Phase B: z2 = W2 h1 + b2 ; t = E s1 ; trace; h2 =======
            float accZ[2][4][4], accT[2][4][4];
            {
                #pragma unroll
                for (int m2 = 0; m2 < 2; ++m2)
                    #pragma unroll
                    for (int nt = 0; nt < 4; ++nt)
                        #pragma unroll
                        for (int e = 0; e < 4; ++e) { accZ[m2][nt][e] = 0.f; accT[m2][nt][e] = 0.f; }

                // GEMM Z: (W2h + W2l) x h1
                #pragma unroll 2
                for (int kc = 0; kc < 16; ++kc) {
                    int k0c = kc * 16;
                    uint32_t bh[8];
                    ldsm_b(&bh[0], h1s, 0,  LDH, k0c, lane);
                    ldsm_b(&bh[4], h1s, 16, LDH, k0c, lane);
                    uint32_t ah[2][4], al[2][4];
                    #pragma unroll
                    for (int m2 = 0; m2 < 2; ++m2) {
                        ldfrag(g_W2hf, 2 * w + m2, 16, kc, lane, ah[m2]);
                        ldfrag(g_W2lf, 2 * w + m2, 16, kc, lane, al[m2]);
                    }
                    #pragma unroll
                    for (int m2 = 0; m2 < 2; ++m2)
                        #pragma unroll
                        for (int nt = 0; nt < 4; ++nt) {
                            uint32_t b0 = bh[(nt >> 1) * 4 + (nt & 1) * 2];
                            uint32_t b1 = bh[(nt >> 1) * 4 + (nt & 1) * 2 + 1];
                            MMA16816(accZ[m2][nt], ah[m2][0], ah[m2][1], ah[m2][2], ah[m2][3], b0, b1);
                        }
                    #pragma unroll
                    for (int m2 = 0; m2 < 2; ++m2)
                        #pragma unroll
                        for (int nt = 0; nt < 4; ++nt) {
                            uint32_t b0 = bh[(nt >> 1) * 4 + (nt & 1) * 2];
                            uint32_t b1 = bh[(nt >> 1) * 4 + (nt & 1) * 2 + 1];
                            MMA16816(accZ[m2][nt], al[m2][0], al[m2][1], al[m2][2], al[m2][3], b0, b1);
                        }
                }
                // GEMM T: (Eh + El) x s1
                #pragma unroll 2
                for (int kc = 0; kc < 16; ++kc) {
                    int k0c = kc * 16;
                    uint32_t bh[8];
                    ldsm_b(&bh[0], s1s, 0,  LDH, k0c, lane);
                    ldsm_b(&bh[4], s1s, 16, LDH, k0c, lane);
                    uint32_t ah[2][4], al[2][4];
                    #pragma unroll
                    for (int m2 = 0; m2 < 2; ++m2) {
                        ldfrag(g_Ehf, 2 * w + m2, 16, kc, lane, ah[m2]);
                        ldfrag(g_Elf, 2 * w + m2, 16, kc, lane, al[m2]);
                    }
                    #pragma unroll
                    for (int m2 = 0; m2 < 2; ++m2)
                        #pragma unroll
                        for (int nt = 0; nt < 4; ++nt) {
                            uint32_t b0 = bh[(nt >> 1) * 4 + (nt & 1) * 2];
                            uint32_t b1 = bh[(nt >> 1) * 4 + (nt & 1) * 2 + 1];
                            MMA16816(accT[m2][nt], ah[m2][0], ah[m2][1], ah[m2][2], ah[m2][3], b0, b1);
                        }
                    #pragma unroll
                    for (int m2 = 0; m2 < 2; ++m2)
                        #pragma unroll
                        for (int nt = 0; nt < 4; ++nt) {
                            uint32_t b0 = bh[(nt >> 1) * 4 + (nt & 1) * 2];
                            uint32_t b1 = bh[(nt >> 1) * 4 + (nt & 1) * 2 + 1];
                            MMA16816(accT[m2][nt], al[m2][0], al[m2][1], al[m2][2], al[m2][3], b0, b1);
                        }
                }
            }
            __syncthreads();                    // all h1/s1 reads done

            // epilogue B: h2 = softplus(z2) into h1 array; trace partials
            {
                #pragma unroll
                for (int nt = 0; nt < 4; ++nt) {
                    float p0 = 0.f, p1 = 0.f;
                    #pragma unroll
                    for (int m2 = 0; m2 < 2; ++m2) {
                        int mrow = 16 * (2 * w + m2);
                        float bm0 = b2g[mrow + qrow], bm1 = b2g[mrow + qrow + 8];
                        #pragma unroll
                        for (int e = 0; e < 4; ++e) {
                            int m = mrow + qrow + ((e >> 1) << 3);
                            int n = nt * 8 + 2 * qcol + (e & 1);
                            float z = accZ[m2][nt][e] + ((e >> 1) ? bm1 : bm0);
                            float t = __expf(-fabsf(z));
                            float u = __fdividef(1.f, 1.f + t);
                            float sp = fmaxf(z, 0.f) + __logf(1.f + t);
                            float sg = (z > 0.f) ? u : 1.f - u;
                            h1s[n * LDH + m] = __float2half(sp);
                            float contrib = sg * accT[m2][nt][e];
                            if (e & 1) p1 += contrib; else p0 += contrib;
                        }
                    }
                    #pragma unroll
                    for (int msk = 4; msk <= 16; msk <<= 1) {
                        p0 += __shfl_xor_sync(0xFFFFFFFFu, p0, msk);
                        p1 += __shfl_xor_sync(0xFFFFFFFFu, p1, msk);
                    }
                    if (qrow == 0) {
                        atomicAdd(&trs[nt * 8 + 2 * qcol], p0);
                        atomicAdd(&trs[nt * 8 + 2 * qcol + 1], p1);
                    }
                }
            }
            __syncthreads();                    // h2 + trs ready

            if (tid < SB) lds[tid] += dt * c_CL[st] * trs[tid];

            // ===== Phase C: dy = W3 h2 + b3 ; k store; stage combine ======
            {
                const int mt = w & 3;           // m-tile over D=64
                const int np = w >> 2;          // 0..1, n-tile pair
                float acc[2][4];
                #pragma unroll
                for (int f = 0; f < 2; ++f)
                    #pragma unroll
                    for (int e = 0; e < 4; ++e) acc[f][e] = 0.f;

                #pragma unroll 4
                for (int kc = 0; kc < 16; ++kc) {
                    int k0c = kc * 16;
                    uint32_t bh[4];
                    ldsm_b(bh, h1s, np * 16, LDH, k0c, lane);
                    uint32_t ah[4], al[4];
                    ldfrag(g_W3hf, mt, 16, kc, lane, ah);
                    ldfrag(g_W3lf, mt, 16, kc, lane, al);
                    MMA16816(acc[0], ah[0], ah[1], ah[2], ah[3], bh[0], bh[1]);
                    MMA16816(acc[1], ah[0], ah[1], ah[2], ah[3], bh[2], bh[3]);
                    MMA16816(acc[0], al[0], al[1], al[2], al[3], bh[0], bh[1]);
                    MMA16816(acc[1], al[0], al[1], al[2], al[3], bh[2], bh[3]);
                }
                // epilogue: bias, store k, Dopri5 combine, write yst (and y)
                float bm0 = b3g[16 * mt + qrow], bm1 = b3g[16 * mt + qrow + 8];
                float alast = c_A[st][st];
                #pragma unroll
                for (int f = 0; f < 2; ++f) {
                    #pragma unroll
                    for (int e = 0; e < 4; ++e) {
                        int dd = 16 * mt + qrow + ((e >> 1) << 3);
                        int s  = (2 * np + f) * 8 + 2 * qcol + (e & 1);
                        float v = acc[f][e] + ((e >> 1) ? bm1 : bm0);   // dy
                        int gidx = (gbase + s) * DB + dd;
                        if (st < 5) g_k[st][gidx] = v;
                        float comb = alast * v;
                        for (int m = 0; m < st; ++m)
                            comb += c_A[st][m] * g_k[m][gidx];
                        float nv = yt[s * LDF + dd] + dt * comb;
                        if (st == 5) yt[s * LDF + dd] = nv;
                        ys[s * LDY + dd] = __float2half(nv);
                    }
                }
            }
        } // stages
    } // steps

    __syncthreads();
    {
        const int d = tid & 63;
        const int srow = tid >> 6;
        #pragma unroll
        for (int c = 0; c < 8; ++c) {
            int s = srow * 8 + c;
            out[(gbase + s) * DB + d] = yt[s * LDF + d];
        }
        if (tid < SB) out[BT * DB + gbase + tid] = lds[tid];
    }
}

// ---------------------------------------------------------------------------
#define SMEM_BYTES ((2 * SB * LDH + SB * LDY) * 2 + (SB * LDF + 2 * SB) * 4)

extern "C" void kernel_launch(void* const* d_in, const int* in_sizes, int n_in,
                              void* d_out, int out_size) {
    const float* x   = (const float*)d_in[0];
    const float* ld0 = (const float*)d_in[1];
    const float* W1  = (const float*)d_in[2];
    const float* b1  = (const float*)d_in[3];
    const float* W2  = (const float*)d_in[4];
    const float* b2  = (const float*)d_in[5];
    const float* W3  = (const float*)d_in[6];
    const float* b3  = (const float*)d_in[7];
    const float* T   = (const float*)d_in[8];
    float* out = (float*)d_out;

    cudaFuncSetAttribute(cnf_main_kernel,
                         cudaFuncAttributeMaxDynamicSharedMemorySize, SMEM_BYTES);

    cnf_prep_kernel<<<HB, HB>>>(W1, W2, W3);
    cnf_main_kernel<<<NBLOCKS, NTHREADS, SMEM_BYTES>>>(x, ld0, b1, b2, b3, T, out);
}

// round 9
// speedup vs baseline: 11.0487x; 1.2487x over previous
#include <cuda_runtime.h>
#include <cuda_fp16.h>
#include <cstdint>

// ---------------------------------------------------------------------------
// CNF Dopri5 solver, tensor-core GEMMs, fp16 2-pass weights (E single-pass).
// R9: k1..k5 in SMEM (no global k traffic); 32 samples/CTA, 256 CTAs,
// 256 threads, 2 CTAs/SM.
// ---------------------------------------------------------------------------

#define DB 64
#define HB 256
#define BT 8192
#define NSTEPS 10
#define SB 32
#define NTHREADS 256
#define NBLOCKS (BT / SB)      // 256

#define LDH 264                // padded k-row for h/s arrays (fp16)
#define LDY 72                 // padded k-row for yst array
#define LDF 68                 // padded row for fp32 y
#define LDK 68                 // padded row for fp32 k stages

typedef __half f16;

// Fragment-packed weights hi/lo fp16: uint4 index = (mtile*KC+kc)*32+lane.
__device__ __align__(16) f16 g_W1hf[HB * DB], g_W1lf[HB * DB];     // M=256,K=64 (KC=4)
__device__ __align__(16) f16 g_W2hf[HB * HB], g_W2lf[HB * HB];     // M=256,K=256 (KC=16)
__device__ __align__(16) f16 g_Ehf [HB * HB];                      // M=256,K=256 (single)
__device__ __align__(16) f16 g_W3hf[DB * HB], g_W3lf[DB * HB];     // M=64, K=256

__constant__ float c_A[6][6] = {
    { 0.2f, 0.f, 0.f, 0.f, 0.f, 0.f },
    { 3.f/40.f, 9.f/40.f, 0.f, 0.f, 0.f, 0.f },
    { 44.f/45.f, -56.f/15.f, 32.f/9.f, 0.f, 0.f, 0.f },
    { 19372.f/6561.f, -25360.f/2187.f, 64448.f/6561.f, -212.f/729.f, 0.f, 0.f },
    { 9017.f/3168.f, -355.f/33.f, 46732.f/5247.f, 49.f/176.f, -5103.f/18656.f, 0.f },
    { 35.f/384.f, 0.f, 500.f/1113.f, 125.f/192.f, -2187.f/6784.f, 11.f/84.f }
};
__constant__ float c_CL[6] = {
    35.f/384.f, 0.f, 500.f/1113.f, 125.f/192.f, -2187.f/6784.f, 11.f/84.f
};

__device__ __forceinline__ void wsplit(float v, f16& hi, f16& lo) {
    hi = __float2half(v);
    lo = __float2half(v - __half2float(hi));
}

// Packed-fragment element index for A element (m,k) of a matrix with KC k-tiles.
__device__ __forceinline__ int pidx(int m, int k, int KC) {
    int mtile = m >> 4;
    int kc    = k >> 4;
    int lane  = (m & 7) * 4 + ((k & 7) >> 1);
    int reg   = ((k >> 3) & 1) * 2 + ((m >> 3) & 1);
    int half_ = k & 1;
    return (((mtile * KC + kc) * 32 + lane) * 4 + reg) * 2 + half_;
}

#define MMA16816(dd, a0, a1, a2, a3, bb0, bb1) \
    asm volatile("mma.sync.aligned.m16n8k16.row.col.f32.f16.f16.f32 " \
        "{%0,%1,%2,%3}, {%4,%5,%6,%7}, {%8,%9}, {%0,%1,%2,%3};" \
        : "+f"(dd[0]), "+f"(dd[1]), "+f"(dd[2]), "+f"(dd[3]) \
        : "r"(a0), "r"(a1), "r"(a2), "r"(a3), "r"(bb0), "r"(bb1))

// ldmatrix.x4: B-fragments for two adjacent n-tiles at k-offset k0c.
__device__ __forceinline__ void ldsm_b(uint32_t r[4], const f16* base,
                                       int nrow0, int ld, int k0c, int lane) {
    int mat = lane >> 3, rr = lane & 7;
    const f16* p = base + (nrow0 + ((mat >> 1) << 3) + rr) * ld
                        + k0c + ((mat & 1) << 3);
    uint32_t saddr = (uint32_t)__cvta_generic_to_shared(p);
    asm volatile("ldmatrix.sync.aligned.m8n8.x4.shared.b16 {%0,%1,%2,%3}, [%4];"
        : "=r"(r[0]), "=r"(r[1]), "=r"(r[2]), "=r"(r[3]) : "r"(saddr));
}

__device__ __forceinline__ void ldfrag(const f16* packed, int mtile, int KC,
                                       int kc, int lane, uint32_t a[4]) {
    uint4 v = ((const uint4*)packed)[(mtile * KC + kc) * 32 + lane];
    a[0] = v.x; a[1] = v.y; a[2] = v.z; a[3] = v.w;
}

// ---------------------------------------------------------------------------
// Prep: split weights hi/lo fp16 into packed fragment layout; E = W2 .* G^T.
// ---------------------------------------------------------------------------
__global__ void cnf_prep_kernel(const float* __restrict__ W1,
                                const float* __restrict__ W2,
                                const float* __restrict__ W3) {
    int i = blockIdx.x;
    int j = threadIdx.x;
    float g = 0.f;
    #pragma unroll
    for (int d = 0; d < DB; ++d)
        g += W1[i * DB + d] * W3[d * HB + j];
    {
        float ev = W2[j * HB + i] * g;     // E[j][i]
        g_Ehf[pidx(j, i, 16)] = __float2half(ev);
    }
    {
        int q = pidx(i, j, 16);
        wsplit(W2[i * HB + j], g_W2hf[q], g_W2lf[q]);
    }
    if (j < DB) {
        int q = pidx(i, j, 4);
        wsplit(W1[i * DB + j], g_W1hf[q], g_W1lf[q]);
    }
    if (i < DB) {
        int q = pidx(i, j, 16);
        wsplit(W3[i * HB + j], g_W3hf[q], g_W3lf[q]);
    }
}

// ---------------------------------------------------------------------------
// Main solver. grid=256, block=256, dyn smem ~91KB, 2 CTAs/SM.
// ---------------------------------------------------------------------------
__global__ void __launch_bounds__(NTHREADS, 2)
cnf_main_kernel(const float* __restrict__ x,
                const float* __restrict__ ld0,
                const float* __restrict__ b1g,
                const float* __restrict__ b2g,
                const float* __restrict__ b3g,
                const float* __restrict__ Tptr,
                float* __restrict__ out) {
    extern __shared__ char smraw[];
    f16* h1s = (f16*)smraw;              // [32][LDH]  h1 (becomes h2)
    f16* s1s = h1s + SB * LDH;           // [32][LDH]  sigmoid
    f16* ys  = s1s + SB * LDH;           // [32][LDY]  stage argument
    float* yt = (float*)(ys + SB * LDY); // [32][LDF]  master y fp32
    float* ks = yt + SB * LDF;           // [5][32][LDK]  k1..k5
    float* trs = ks + 5 * SB * LDK;
    float* lds = trs + SB;

    const int tid  = threadIdx.x;
    const int lane = tid & 31;
    const int w    = tid >> 5;           // warp 0..7
    const int qrow = lane >> 2;
    const int qcol = lane & 3;
    const int gbase = blockIdx.x * SB;

    const float dt = Tptr[0] * (1.0f / NSTEPS);

    {
        const int d = tid & 63;
        const int srow = tid >> 6;       // 0..3
        #pragma unroll
        for (int c = 0; c < 8; ++c) {
            int s = srow * 8 + c;
            float v = x[(gbase + s) * DB + d];
            yt[s * LDF + d] = v;
            ys[s * LDY + d] = __float2half(v);
        }
        if (tid < SB) lds[tid] = ld0[gbase + tid];
    }

    for (int step = 0; step < NSTEPS; ++step) {
        for (int st = 0; st < 6; ++st) {
            __syncthreads();                    // yst ready
            if (tid < SB) trs[tid] = 0.f;

            // ================= Phase A: z1 = W1 yst + b1 =================
            {
                float acc[2][4][4];
                #pragma unroll
                for (int m2 = 0; m2 < 2; ++m2)
                    #pragma unroll
                    for (int nt = 0; nt < 4; ++nt)
                        #pragma unroll
                        for (int e = 0; e < 4; ++e) acc[m2][nt][e] = 0.f;

                #pragma unroll
                for (int kc = 0; kc < 4; ++kc) {
                    int k0c = kc * 16;
                    uint32_t bh[8];
                    ldsm_b(&bh[0], ys, 0,  LDY, k0c, lane);
                    ldsm_b(&bh[4], ys, 16, LDY, k0c, lane);
                    uint32_t ah[2][4], al[2][4];
                    #pragma unroll
                    for (int m2 = 0; m2 < 2; ++m2) {
                        ldfrag(g_W1hf, 2 * w + m2, 4, kc, lane, ah[m2]);
                        ldfrag(g_W1lf, 2 * w + m2, 4, kc, lane, al[m2]);
                    }
                    #pragma unroll
                    for (int m2 = 0; m2 < 2; ++m2)
                        #pragma unroll
                        for (int nt = 0; nt < 4; ++nt) {
                            uint32_t b0 = bh[(nt >> 1) * 4 + (nt & 1) * 2];
                            uint32_t b1 = bh[(nt >> 1) * 4 + (nt & 1) * 2 + 1];
                            MMA16816(acc[m2][nt], ah[m2][0], ah[m2][1], ah[m2][2], ah[m2][3], b0, b1);
                        }
                    #pragma unroll
                    for (int m2 = 0; m2 < 2; ++m2)
                        #pragma unroll
                        for (int nt = 0; nt < 4; ++nt) {
                            uint32_t b0 = bh[(nt >> 1) * 4 + (nt & 1) * 2];
                            uint32_t b1 = bh[(nt >> 1) * 4 + (nt & 1) * 2 + 1];
                            MMA16816(acc[m2][nt], al[m2][0], al[m2][1], al[m2][2], al[m2][3], b0, b1);
                        }
                }
                // epilogue A
                #pragma unroll
                for (int m2 = 0; m2 < 2; ++m2) {
                    int mrow = 16 * (2 * w + m2);
                    float bm0 = b1g[mrow + qrow], bm1 = b1g[mrow + qrow + 8];
                    #pragma unroll
                    for (int nt = 0; nt < 4; ++nt) {
                        #pragma unroll
                        for (int e = 0; e < 4; ++e) {
                            int m = mrow + qrow + ((e >> 1) << 3);
                            int n = nt * 8 + 2 * qcol + (e & 1);
                            float z = acc[m2][nt][e] + ((e >> 1) ? bm1 : bm0);
                            float t = __expf(-fabsf(z));
                            float u = __fdividef(1.f, 1.f + t);
                            float sp = fmaxf(z, 0.f) + __logf(1.f + t);
                            float sg = (z > 0.f) ? u : 1.f - u;
                            h1s[n * LDH + m] = __float2half(sp);
                            s1s[n * LDH + m] = __float2half(sg);
                        }
                    }
                }
            }
            __syncthreads();                    // h1/s1 ready

            // ===== Phase B: z2 = W2 h1 + b2 ; t = E s1 ; trace; h2 =======
            float accZ[2][4][4], accT[2][4][4];
            {
                #pragma unroll
                for (int m2 = 0; m2 < 2; ++m2)
                    #pragma unroll
                    for (int nt = 0; nt < 4; ++nt)
                        #pragma unroll
                        for (int e = 0; e < 4; ++e) { accZ[m2][nt][e] = 0.f; accT[m2][nt][e] = 0.f; }

                // GEMM Z: (W2h + W2l) x h1
                #pragma unroll 2
                for (int kc = 0; kc < 16; ++kc) {
                    int k0c = kc * 16;
                    uint32_t bh[8];
                    ldsm_b(&bh[0], h1s, 0,  LDH, k0c, lane);
                    ldsm_b(&bh[4], h1s, 16, LDH, k0c, lane);
                    uint32_t ah[2][4], al[2][4];
                    #pragma unroll
                    for (int m2 = 0; m2 < 2; ++m2) {
                        ldfrag(g_W2hf, 2 * w + m2, 16, kc, lane, ah[m2]);
                        ldfrag(g_W2lf, 2 * w + m2, 16, kc, lane, al[m2]);
                    }
                    #pragma unroll
                    for (int m2 = 0; m2 < 2; ++m2)
                        #pragma unroll
                        for (int nt = 0; nt < 4; ++nt) {
                            uint32_t b0 = bh[(nt >> 1) * 4 + (nt & 1) * 2];
                            uint32_t b1 = bh[(nt >> 1) * 4 + (nt & 1) * 2 + 1];
                            MMA16816(accZ[m2][nt], ah[m2][0], ah[m2][1], ah[m2][2], ah[m2][3], b0, b1);
                        }
                    #pragma unroll
                    for (int m2 = 0; m2 < 2; ++m2)
                        #pragma unroll
                        for (int nt = 0; nt < 4; ++nt) {
                            uint32_t b0 = bh[(nt >> 1) * 4 + (nt & 1) * 2];
                            uint32_t b1 = bh[(nt >> 1) * 4 + (nt & 1) * 2 + 1];
                            MMA16816(accZ[m2][nt], al[m2][0], al[m2][1], al[m2][2], al[m2][3], b0, b1);
                        }
                }
                // GEMM T: Eh x s1 (single pass — feeds logdet only)
                #pragma unroll 2
                for (int kc = 0; kc < 16; ++kc) {
                    int k0c = kc * 16;
                    uint32_t bh[8];
                    ldsm_b(&bh[0], s1s, 0,  LDH, k0c, lane);
                    ldsm_b(&bh[4], s1s, 16, LDH, k0c, lane);
                    uint32_t ah[2][4];
                    #pragma unroll
                    for (int m2 = 0; m2 < 2; ++m2)
                        ldfrag(g_Ehf, 2 * w + m2, 16, kc, lane, ah[m2]);
                    #pragma unroll
                    for (int m2 = 0; m2 < 2; ++m2)
                        #pragma unroll
                        for (int nt = 0; nt < 4; ++nt) {
                            uint32_t b0 = bh[(nt >> 1) * 4 + (nt & 1) * 2];
                            uint32_t b1 = bh[(nt >> 1) * 4 + (nt & 1) * 2 + 1];
                            MMA16816(accT[m2][nt], ah[m2][0], ah[m2][1], ah[m2][2], ah[m2][3], b0, b1);
                        }
                }
            }
            __syncthreads();                    // all h1/s1 reads done

            // epilogue B: h2 = softplus(z2) into h1 array; trace partials
            {
                #pragma unroll
                for (int nt = 0; nt < 4; ++nt) {
                    float p0 = 0.f, p1 = 0.f;
                    #pragma unroll
                    for (int m2 = 0; m2 < 2; ++m2) {
                        int mrow = 16 * (2 * w + m2);
                        float bm0 = b2g[mrow + qrow], bm1 = b2g[mrow + qrow + 8];
                        #pragma unroll
                        for (int e = 0; e < 4; ++e) {
                            int m = mrow + qrow + ((e >> 1) << 3);
                            int n = nt * 8 + 2 * qcol + (e & 1);
                            float z = accZ[m2][nt][e] + ((e >> 1) ? bm1 : bm0);
                            float t = __expf(-fabsf(z));
                            float u = __fdividef(1.f, 1.f + t);
                            float sp = fmaxf(z, 0.f) + __logf(1.f + t);
                            float sg = (z > 0.f) ? u : 1.f - u;
                            h1s[n * LDH + m] = __float2half(sp);
                            float contrib = sg * accT[m2][nt][e];
                            if (e & 1) p1 += contrib; else p0 += contrib;
                        }
                    }
                    #pragma unroll
                    for (int msk = 4; msk <= 16; msk <<= 1) {
                        p0 += __shfl_xor_sync(0xFFFFFFFFu, p0, msk);
                        p1 += __shfl_xor_sync(0xFFFFFFFFu, p1, msk);
                    }
                    if (qrow == 0) {
                        atomicAdd(&trs[nt * 8 + 2 * qcol], p0);
                        atomicAdd(&trs[nt * 8 + 2 * qcol + 1], p1);
                    }
                }
            }
            __syncthreads();                    // h2 + trs ready

            if (tid < SB) lds[tid] += dt * c_CL[st] * trs[tid];

            // ===== Phase C: dy = W3 h2 + b3 ; k store; stage combine ======
            {
                const int mt = w & 3;           // m-tile over D=64
                const int np = w >> 2;          // 0..1, n-tile pair
                float acc[2][4];
                #pragma unroll
                for (int f = 0; f < 2; ++f)
                    #pragma unroll
                    for (int e = 0; e < 4; ++e) acc[f][e] = 0.f;

                #pragma unroll 4
                for (int kc = 0; kc < 16; ++kc) {
                    int k0c = kc * 16;
                    uint32_t bh[4];
                    ldsm_b(bh, h1s, np * 16, LDH, k0c, lane);
                    uint32_t ah[4], al[4];
                    ldfrag(g_W3hf, mt, 16, kc, lane, ah);
                    ldfrag(g_W3lf, mt, 16, kc, lane, al);
                    MMA16816(acc[0], ah[0], ah[1], ah[2], ah[3], bh[0], bh[1]);
                    MMA16816(acc[1], ah[0], ah[1], ah[2], ah[3], bh[2], bh[3]);
                    MMA16816(acc[0], al[0], al[1], al[2], al[3], bh[0], bh[1]);
                    MMA16816(acc[1], al[0], al[1], al[2], al[3], bh[2], bh[3]);
                }
                // epilogue: bias, store k (SMEM), Dopri5 combine, write yst/y
                float bm0 = b3g[16 * mt + qrow], bm1 = b3g[16 * mt + qrow + 8];
                float alast = c_A[st][st];
                #pragma unroll
                for (int f = 0; f < 2; ++f) {
                    #pragma unroll
                    for (int e = 0; e < 4; ++e) {
                        int dd = 16 * mt + qrow + ((e >> 1) << 3);
                        int s  = (2 * np + f) * 8 + 2 * qcol + (e & 1);
                        float v = acc[f][e] + ((e >> 1) ? bm1 : bm0);   // dy
                        if (st < 5) ks[(st * SB + s) * LDK + dd] = v;
                        float comb = alast * v;
                        for (int m = 0; m < st; ++m)
                            comb += c_A[st][m] * ks[(m * SB + s) * LDK + dd];
                        float nv = yt[s * LDF + dd] + dt * comb;
                        if (st == 5) yt[s * LDF + dd] = nv;
                        ys[s * LDY + dd] = __float2half(nv);
                    }
                }
            }
        } // stages
    } // steps

    __syncthreads();
    {
        const int d = tid & 63;
        const int srow = tid >> 6;
        #pragma unroll
        for (int c = 0; c < 8; ++c) {
            int s = srow * 8 + c;
            out[(gbase + s) * DB + d] = yt[s * LDF + d];
        }
        if (tid < SB) out[BT * DB + gbase + tid] = lds[tid];
    }
}

// ---------------------------------------------------------------------------
#define SMEM_BYTES ((2 * SB * LDH + SB * LDY) * 2 + \
                    (SB * LDF + 5 * SB * LDK + 2 * SB) * 4)

extern "C" void kernel_launch(void* const* d_in, const int* in_sizes, int n_in,
                              void* d_out, int out_size) {
    const float* x   = (const float*)d_in[0];
    const float* ld0 = (const float*)d_in[1];
    const float* W1  = (const float*)d_in[2];
    const float* b1  = (const float*)d_in[3];
    const float* W2  = (const float*)d_in[4];
    const float* b2  = (const float*)d_in[5];
    const float* W3  = (const float*)d_in[6];
    const float* b3  = (const float*)d_in[7];
    const float* T   = (const float*)d_in[8];
    float* out = (float*)d_out;

    cudaFuncSetAttribute(cnf_main_kernel,
                         cudaFuncAttributeMaxDynamicSharedMemorySize, SMEM_BYTES);

    cnf_prep_kernel<<<HB, HB>>>(W1, W2, W3);
    cnf_main_kernel<<<NBLOCKS, NTHREADS, SMEM_BYTES>>>(x, ld0, b1, b2, b3, T, out);
}